// round 1
// baseline (speedup 1.0000x reference)
#include <cuda_runtime.h>
#include <math.h>

// Problem constants
#define BB   4
#define TT   2048
#define DD   512
#define HH   8
#define DHD  64
#define MR   (BB*TT)       // 8192 rows
#define QKVN (3*DD)        // 1536

// Scratch (device globals -- allocation-free)
__device__ float g_qkv[MR * QKVN];        // raw qkv projection [row][1536]
__device__ float g_q[BB*HH*TT*DHD];       // [b,h,t,d]
__device__ float g_k[BB*HH*TT*DHD];
__device__ float g_v[BB*HH*TT*DHD];
__device__ float g_att[MR * DD];          // attention output [b*t][D]

// ---------------------------------------------------------------------------
// GEMM: C[M,N] = A[M,K] @ Bw[N,K]^T + bias[N]
// BM=BN=128, BK=16, 256 threads, 8x8 per thread. Smem staged transposed
// (As[k][m]) so the inner loop reads contiguous float4s (conflict-free).
// ---------------------------------------------------------------------------
#define GBM 128
#define GBN 128
#define GBK 16

__global__ __launch_bounds__(256, 2)
void gemm_bias_kernel(const float* __restrict__ A,
                      const float* __restrict__ Bw,
                      const float* __restrict__ bias,
                      float* __restrict__ C,
                      int N, int K)
{
    __shared__ float As[GBK][GBM + 4];
    __shared__ float Bs[GBK][GBN + 4];

    const int tid = threadIdx.x;
    const int tx  = tid & 15;       // 0..15 -> N micro
    const int ty  = tid >> 4;       // 0..15 -> M micro
    const int mBase = blockIdx.y * GBM;
    const int nBase = blockIdx.x * GBN;

    float acc[8][8];
#pragma unroll
    for (int i = 0; i < 8; i++)
#pragma unroll
        for (int j = 0; j < 8; j++) acc[i][j] = 0.0f;

    for (int k0 = 0; k0 < K; k0 += GBK) {
        // Load A tile: 128x16 floats = 512 float4; 2 per thread, transposed store
#pragma unroll
        for (int l = 0; l < 2; l++) {
            int f   = tid + l * 256;          // float4 index
            int row = f >> 2;                 // 16 floats per row = 4 float4
            int c4  = (f & 3) << 2;
            float4 v = *(const float4*)&A[(size_t)(mBase + row) * K + k0 + c4];
            As[c4 + 0][row] = v.x;
            As[c4 + 1][row] = v.y;
            As[c4 + 2][row] = v.z;
            As[c4 + 3][row] = v.w;
        }
        // Load B tile (Bw is N x K row-major)
#pragma unroll
        for (int l = 0; l < 2; l++) {
            int f   = tid + l * 256;
            int row = f >> 2;
            int c4  = (f & 3) << 2;
            float4 v = *(const float4*)&Bw[(size_t)(nBase + row) * K + k0 + c4];
            Bs[c4 + 0][row] = v.x;
            Bs[c4 + 1][row] = v.y;
            Bs[c4 + 2][row] = v.z;
            Bs[c4 + 3][row] = v.w;
        }
        __syncthreads();

#pragma unroll
        for (int k = 0; k < GBK; k++) {
            float a[8], bb[8];
            *(float4*)&a[0]  = *(const float4*)&As[k][ty * 8];
            *(float4*)&a[4]  = *(const float4*)&As[k][ty * 8 + 4];
            *(float4*)&bb[0] = *(const float4*)&Bs[k][tx * 8];
            *(float4*)&bb[4] = *(const float4*)&Bs[k][tx * 8 + 4];
#pragma unroll
            for (int i = 0; i < 8; i++)
#pragma unroll
                for (int j = 0; j < 8; j++)
                    acc[i][j] = fmaf(a[i], bb[j], acc[i][j]);
        }
        __syncthreads();
    }

    // Epilogue: bias + store
    float bv[8];
#pragma unroll
    for (int j = 0; j < 8; j++) bv[j] = bias[nBase + tx * 8 + j];
#pragma unroll
    for (int i = 0; i < 8; i++) {
        float* crow = &C[(size_t)(mBase + ty * 8 + i) * N + nBase + tx * 8];
        float4 v0 = make_float4(acc[i][0] + bv[0], acc[i][1] + bv[1],
                                acc[i][2] + bv[2], acc[i][3] + bv[3]);
        float4 v1 = make_float4(acc[i][4] + bv[4], acc[i][5] + bv[5],
                                acc[i][6] + bv[6], acc[i][7] + bv[7]);
        *(float4*)&crow[0] = v0;
        *(float4*)&crow[4] = v1;
    }
}

// ---------------------------------------------------------------------------
// RoPE + scatter: g_qkv [b*t][1536] -> g_q/g_k/g_v [b,h,t,d]
// One thread per rotation pair (j, j+32) of one head.
// ---------------------------------------------------------------------------
__global__ void rope_scatter_kernel()
{
    int idx = blockIdx.x * blockDim.x + threadIdx.x;   // over BB*TT*HH*32
    if (idx >= BB * TT * HH * 32) return;
    const int j  = idx & 31;
    const int h  = (idx >> 5) & 7;
    const int bt = idx >> 8;
    const int b  = bt / TT;
    const int t  = bt - b * TT;

    const float* row = g_qkv + (size_t)bt * QKVN;
    const int base = h * DHD;

    // angle = t * 10000^(-2j/64)
    float inv = powf(10000.0f, -(float)(2 * j) * (1.0f / 64.0f));
    float ang = (float)t * inv;
    float c = cosf(ang);
    float s = sinf(ang);

    float q1 = row[base + j],        q2 = row[base + j + 32];
    float k1 = row[DD + base + j],   k2 = row[DD + base + j + 32];
    float v1 = row[2*DD + base + j], v2 = row[2*DD + base + j + 32];

    float qo1 = q1 * c - q2 * s;
    float qo2 = q2 * c + q1 * s;
    float ko1 = k1 * c - k2 * s;
    float ko2 = k2 * c + k1 * s;

    size_t o = ((size_t)(b * HH + h) * TT + t) * DHD;
    g_q[o + j]      = qo1;
    g_q[o + j + 32] = qo2;
    g_k[o + j]      = ko1;
    g_k[o + j + 32] = ko2;
    g_v[o + j]      = v1;
    g_v[o + j + 32] = v2;
}

// ---------------------------------------------------------------------------
// Flash attention: one block per (b,h, 64-row q tile). 256 threads, 4x4 micro.
// Online softmax; P staged through smem for the PV product.
// Output written to g_att in [b*t][D] layout (ready for proj GEMM).
// ---------------------------------------------------------------------------
#define ATT_SMEM ((64*65*3 + 64*64) * 4)   // Qs,Ks,Ps padded + Vs = 66304 B

__global__ __launch_bounds__(256, 3)
void attn_kernel(const float* __restrict__ mask)
{
    extern __shared__ float sm[];
    float* Qs = sm;               // 64 x 65
    float* Ks = Qs + 64 * 65;     // 64 x 65
    float* Ps = Ks + 64 * 65;     // 64 x 65
    float* Vs = Ps + 64 * 65;     // 64 x 64

    const int bh = blockIdx.y;          // 0..31
    const int b  = bh >> 3;
    const int h  = bh & 7;
    const int q0 = blockIdx.x * 64;
    const int tid = threadIdx.x;
    const int tx  = tid & 15;
    const int ty  = tid >> 4;

    const float scale = 0.125f;         // 1/sqrt(64)

    // Load Q tile
    const float* qptr = g_q + ((size_t)bh * TT + q0) * DHD;
    for (int l = tid; l < 64 * 64; l += 256) {
        int r = l >> 6, c = l & 63;
        Qs[r * 65 + c] = qptr[r * DHD + c];
    }

    float m_i[4], l_i[4], o[4][4];
#pragma unroll
    for (int i = 0; i < 4; i++) {
        m_i[i] = -1e30f;
        l_i[i] = 0.0f;
#pragma unroll
        for (int j = 0; j < 4; j++) o[i][j] = 0.0f;
    }

    const float* kbase = g_k + (size_t)bh * TT * DHD;
    const float* vbase = g_v + (size_t)bh * TT * DHD;

    for (int kt = 0; kt < TT / 64; kt++) {
        const int k0 = kt * 64;
        // Load K/V tiles
        const float* kptr = kbase + (size_t)k0 * DHD;
        const float* vptr = vbase + (size_t)k0 * DHD;
        for (int l = tid; l < 64 * 64; l += 256) {
            int r = l >> 6, c = l & 63;
            Ks[r * 65 + c] = kptr[r * DHD + c];
            Vs[r * 64 + c] = vptr[r * DHD + c];
        }
        __syncthreads();

        // S = Q K^T
        float s[4][4];
#pragma unroll
        for (int i = 0; i < 4; i++)
#pragma unroll
            for (int j = 0; j < 4; j++) s[i][j] = 0.0f;

#pragma unroll 8
        for (int k = 0; k < 64; k++) {
            float qf[4], kf[4];
#pragma unroll
            for (int i = 0; i < 4; i++) qf[i] = Qs[(ty * 4 + i) * 65 + k];
#pragma unroll
            for (int j = 0; j < 4; j++) kf[j] = Ks[(tx * 4 + j) * 65 + k];
#pragma unroll
            for (int i = 0; i < 4; i++)
#pragma unroll
                for (int j = 0; j < 4; j++)
                    s[i][j] = fmaf(qf[i], kf[j], s[i][j]);
        }

        // scale + mask
#pragma unroll
        for (int i = 0; i < 4; i++) {
            const float* mrow = mask + ((size_t)b * TT + (q0 + ty * 4 + i)) * TT
                              + k0 + tx * 4;
            float4 mv = *(const float4*)mrow;
            s[i][0] = fmaf(s[i][0], scale, mv.x);
            s[i][1] = fmaf(s[i][1], scale, mv.y);
            s[i][2] = fmaf(s[i][2], scale, mv.z);
            s[i][3] = fmaf(s[i][3], scale, mv.w);
        }

        // Online softmax update
        float corr[4];
#pragma unroll
        for (int i = 0; i < 4; i++) {
            float mt = fmaxf(fmaxf(s[i][0], s[i][1]), fmaxf(s[i][2], s[i][3]));
#pragma unroll
            for (int off = 8; off; off >>= 1)
                mt = fmaxf(mt, __shfl_xor_sync(0xffffffffu, mt, off, 16));
            float m_new = fmaxf(m_i[i], mt);
            corr[i] = __expf(m_i[i] - m_new);
            m_i[i] = m_new;

            float rs = 0.0f;
#pragma unroll
            for (int j = 0; j < 4; j++) {
                s[i][j] = __expf(s[i][j] - m_new);
                rs += s[i][j];
            }
#pragma unroll
            for (int off = 8; off; off >>= 1)
                rs += __shfl_xor_sync(0xffffffffu, rs, off, 16);
            l_i[i] = l_i[i] * corr[i] + rs;
#pragma unroll
            for (int j = 0; j < 4; j++) o[i][j] *= corr[i];
        }

        // Stage P for the PV product
#pragma unroll
        for (int i = 0; i < 4; i++)
#pragma unroll
            for (int j = 0; j < 4; j++)
                Ps[(ty * 4 + i) * 65 + tx * 4 + j] = s[i][j];
        __syncthreads();

        // O += P V
#pragma unroll 8
        for (int k = 0; k < 64; k++) {
            float pf[4], vf[4];
#pragma unroll
            for (int i = 0; i < 4; i++) pf[i] = Ps[(ty * 4 + i) * 65 + k];
#pragma unroll
            for (int j = 0; j < 4; j++) vf[j] = Vs[k * 64 + tx * 4 + j];
#pragma unroll
            for (int i = 0; i < 4; i++)
#pragma unroll
                for (int j = 0; j < 4; j++)
                    o[i][j] = fmaf(pf[i], vf[j], o[i][j]);
        }
        __syncthreads();   // before K/V/P overwritten next iteration
    }

    // Normalize + write to g_att [b*t][D]
#pragma unroll
    for (int i = 0; i < 4; i++) {
        float inv_l = 1.0f / l_i[i];
        size_t row = (size_t)b * TT + (q0 + ty * 4 + i);
        float* arow = g_att + row * DD + h * DHD + tx * 4;
        float4 v = make_float4(o[i][0] * inv_l, o[i][1] * inv_l,
                               o[i][2] * inv_l, o[i][3] * inv_l);
        *(float4*)arow = v;
    }
}

// ---------------------------------------------------------------------------
// Launch
// ---------------------------------------------------------------------------
extern "C" void kernel_launch(void* const* d_in, const int* in_sizes, int n_in,
                              void* d_out, int out_size)
{
    const float* x      = (const float*)d_in[0];
    const float* mask   = (const float*)d_in[1];
    const float* w_qkv  = (const float*)d_in[2];
    const float* b_qkv  = (const float*)d_in[3];
    const float* w_proj = (const float*)d_in[4];
    const float* b_proj = (const float*)d_in[5];
    float* out = (float*)d_out;

    float* qkv;  cudaGetSymbolAddress((void**)&qkv,  g_qkv);
    float* att;  cudaGetSymbolAddress((void**)&att,  g_att);

    // 1) QKV projection: [8192,1536] = x[8192,512] @ w_qkv^T + b_qkv
    {
        dim3 grid(QKVN / GBN, MR / GBM);
        gemm_bias_kernel<<<grid, 256>>>(x, w_qkv, b_qkv, qkv, QKVN, DD);
    }

    // 2) RoPE + scatter to [b,h,t,d]
    {
        int total = BB * TT * HH * 32;
        rope_scatter_kernel<<<(total + 255) / 256, 256>>>();
    }

    // 3) Flash attention
    {
        cudaFuncSetAttribute(attn_kernel,
                             cudaFuncAttributeMaxDynamicSharedMemorySize,
                             ATT_SMEM);
        dim3 grid(TT / 64, BB * HH);
        attn_kernel<<<grid, 256, ATT_SMEM>>>(mask);
    }

    // 4) Output projection: out[8192,512] = att @ w_proj^T + b_proj
    {
        dim3 grid(DD / GBN, MR / GBM);
        gemm_bias_kernel<<<grid, 256>>>(att, w_proj, b_proj, out, DD, DD);
    }
}

// round 2
// speedup vs baseline: 1.0840x; 1.0840x over previous
#include <cuda_runtime.h>
#include <math.h>

// Problem constants
#define BB   4
#define TT   2048
#define DD   512
#define HH   8
#define DHD  64
#define MR   (BB*TT)       // 8192 rows
#define QKVN (3*DD)        // 1536

// Scratch (device globals -- allocation-free)
__device__ float g_qkv[MR * QKVN];        // raw qkv projection [row][1536]
__device__ float g_q[BB*HH*TT*DHD];       // [b,h,t,d]
__device__ float g_k[BB*HH*TT*DHD];
__device__ float g_v[BB*HH*TT*DHD];
__device__ float g_att[MR * DD];          // attention output [b*t][D]

// ---------------------------------------------------------------------------
// GEMM: C[M,N] = A[M,K] @ Bw[N,K]^T + bias[N]   (unchanged from R1)
// ---------------------------------------------------------------------------
#define GBM 128
#define GBN 128
#define GBK 16

__global__ __launch_bounds__(256, 2)
void gemm_bias_kernel(const float* __restrict__ A,
                      const float* __restrict__ Bw,
                      const float* __restrict__ bias,
                      float* __restrict__ C,
                      int N, int K)
{
    __shared__ float As[GBK][GBM + 4];
    __shared__ float Bs[GBK][GBN + 4];

    const int tid = threadIdx.x;
    const int tx  = tid & 15;
    const int ty  = tid >> 4;
    const int mBase = blockIdx.y * GBM;
    const int nBase = blockIdx.x * GBN;

    float acc[8][8];
#pragma unroll
    for (int i = 0; i < 8; i++)
#pragma unroll
        for (int j = 0; j < 8; j++) acc[i][j] = 0.0f;

    for (int k0 = 0; k0 < K; k0 += GBK) {
#pragma unroll
        for (int l = 0; l < 2; l++) {
            int f   = tid + l * 256;
            int row = f >> 2;
            int c4  = (f & 3) << 2;
            float4 v = *(const float4*)&A[(size_t)(mBase + row) * K + k0 + c4];
            As[c4 + 0][row] = v.x;
            As[c4 + 1][row] = v.y;
            As[c4 + 2][row] = v.z;
            As[c4 + 3][row] = v.w;
        }
#pragma unroll
        for (int l = 0; l < 2; l++) {
            int f   = tid + l * 256;
            int row = f >> 2;
            int c4  = (f & 3) << 2;
            float4 v = *(const float4*)&Bw[(size_t)(nBase + row) * K + k0 + c4];
            Bs[c4 + 0][row] = v.x;
            Bs[c4 + 1][row] = v.y;
            Bs[c4 + 2][row] = v.z;
            Bs[c4 + 3][row] = v.w;
        }
        __syncthreads();

#pragma unroll
        for (int k = 0; k < GBK; k++) {
            float a[8], bb[8];
            *(float4*)&a[0]  = *(const float4*)&As[k][ty * 8];
            *(float4*)&a[4]  = *(const float4*)&As[k][ty * 8 + 4];
            *(float4*)&bb[0] = *(const float4*)&Bs[k][tx * 8];
            *(float4*)&bb[4] = *(const float4*)&Bs[k][tx * 8 + 4];
#pragma unroll
            for (int i = 0; i < 8; i++)
#pragma unroll
                for (int j = 0; j < 8; j++)
                    acc[i][j] = fmaf(a[i], bb[j], acc[i][j]);
        }
        __syncthreads();
    }

    float bv[8];
#pragma unroll
    for (int j = 0; j < 8; j++) bv[j] = bias[nBase + tx * 8 + j];
#pragma unroll
    for (int i = 0; i < 8; i++) {
        float* crow = &C[(size_t)(mBase + ty * 8 + i) * N + nBase + tx * 8];
        float4 v0 = make_float4(acc[i][0] + bv[0], acc[i][1] + bv[1],
                                acc[i][2] + bv[2], acc[i][3] + bv[3]);
        float4 v1 = make_float4(acc[i][4] + bv[4], acc[i][5] + bv[5],
                                acc[i][6] + bv[6], acc[i][7] + bv[7]);
        *(float4*)&crow[0] = v0;
        *(float4*)&crow[4] = v1;
    }
}

// ---------------------------------------------------------------------------
// RoPE + scatter
// ---------------------------------------------------------------------------
__global__ void rope_scatter_kernel()
{
    int idx = blockIdx.x * blockDim.x + threadIdx.x;
    if (idx >= BB * TT * HH * 32) return;
    const int j  = idx & 31;
    const int h  = (idx >> 5) & 7;
    const int bt = idx >> 8;
    const int b  = bt / TT;
    const int t  = bt - b * TT;

    const float* row = g_qkv + (size_t)bt * QKVN;
    const int base = h * DHD;

    // inv_freq = 10000^(-j/32) computed via exp2
    float inv = exp2f(-(float)j * 0.41524103736593f);  // log2(10000)/32
    float ang = (float)t * inv;
    float s, c;
    sincosf(ang, &s, &c);

    float q1 = row[base + j],        q2 = row[base + j + 32];
    float k1 = row[DD + base + j],   k2 = row[DD + base + j + 32];
    float v1 = row[2*DD + base + j], v2 = row[2*DD + base + j + 32];

    size_t o = ((size_t)(b * HH + h) * TT + t) * DHD;
    g_q[o + j]      = q1 * c - q2 * s;
    g_q[o + j + 32] = q2 * c + q1 * s;
    g_k[o + j]      = k1 * c - k2 * s;
    g_k[o + j + 32] = k2 * c + k1 * s;
    g_v[o + j]      = v1;
    g_v[o + j + 32] = v2;
}

// ---------------------------------------------------------------------------
// Flash attention v2: 128 q-rows x 64 k-cols per block, 256 threads, 8x4 micro.
// Qt/Kt staged TRANSPOSED ([d][row]) so QK^T inner loop is rank-1 updates with
// broadcast q-reads and conflict-free float4 k-reads. V natural [k][d], P
// natural [q][k], all smem traffic at the bandwidth floor.
// ---------------------------------------------------------------------------
#define QTILE 128
#define KTILE 64
#define QT_STRIDE 132      // 128 + 4, 16B-aligned rows
#define KT_STRIDE 68       // 64 + 4
#define ATT_SMEM ((64*QT_STRIDE + 64*KT_STRIDE + 64*KT_STRIDE + 128*KT_STRIDE) * 4)

__global__ __launch_bounds__(256, 2)
void attn_kernel(const float* __restrict__ mask)
{
    extern __shared__ float sm[];
    float* Qt = sm;                         // [64][132]  (d-major, q cols)
    float* Kt = Qt + 64 * QT_STRIDE;        // [64][68]   (d-major, k cols)
    float* Vs = Kt + 64 * KT_STRIDE;        // [64][68]   (k-major, d cols)
    float* Ps = Vs + 64 * KT_STRIDE;        // [128][68]  (q-major, k cols)

    const int bh  = blockIdx.y;             // 0..31
    const int b   = bh >> 3;
    const int h   = bh & 7;
    const int q0  = blockIdx.x * QTILE;
    const int tid = threadIdx.x;
    const int tx  = tid & 15;               // k/d micro (4 wide)
    const int ty  = tid >> 4;               // q micro (8 tall)

    const float scale = 0.125f;

    // Load Q tile transposed: Qt[d][qrow]
    const float* qptr = g_q + ((size_t)bh * TT + q0) * DHD;
    for (int l = tid; l < QTILE * 16; l += 256) {     // float4 count
        int r  = l >> 4;                              // q row
        int c4 = (l & 15) * 4;                        // d
        float4 v = *(const float4*)&qptr[r * DHD + c4];
        Qt[(c4 + 0) * QT_STRIDE + r] = v.x;
        Qt[(c4 + 1) * QT_STRIDE + r] = v.y;
        Qt[(c4 + 2) * QT_STRIDE + r] = v.z;
        Qt[(c4 + 3) * QT_STRIDE + r] = v.w;
    }

    float m_i[8], l_i[8], o[8][4];
#pragma unroll
    for (int i = 0; i < 8; i++) {
        m_i[i] = -1e30f;
        l_i[i] = 0.0f;
#pragma unroll
        for (int j = 0; j < 4; j++) o[i][j] = 0.0f;
    }

    const float* kbase = g_k + (size_t)bh * TT * DHD;
    const float* vbase = g_v + (size_t)bh * TT * DHD;
    const float* mbase = mask + ((size_t)b * TT + q0) * TT;

    for (int kt = 0; kt < TT / KTILE; kt++) {
        const int k0 = kt * KTILE;
        __syncthreads();   // protect Kt/Vs/Ps from previous-iter readers (and Q load)

        // Load K (transposed) and V (natural)
        const float* kptr = kbase + (size_t)k0 * DHD;
        const float* vptr = vbase + (size_t)k0 * DHD;
        for (int l = tid; l < KTILE * 16; l += 256) {
            int r  = l >> 4;
            int c4 = (l & 15) * 4;
            float4 kv = *(const float4*)&kptr[r * DHD + c4];
            Kt[(c4 + 0) * KT_STRIDE + r] = kv.x;
            Kt[(c4 + 1) * KT_STRIDE + r] = kv.y;
            Kt[(c4 + 2) * KT_STRIDE + r] = kv.z;
            Kt[(c4 + 3) * KT_STRIDE + r] = kv.w;
            float4 vv = *(const float4*)&vptr[r * DHD + c4];
            *(float4*)&Vs[r * KT_STRIDE + c4] = vv;
        }
        __syncthreads();

        // S = Q K^T  (rank-1 updates over d)
        float s[8][4];
#pragma unroll
        for (int i = 0; i < 8; i++)
#pragma unroll
            for (int j = 0; j < 4; j++) s[i][j] = 0.0f;

#pragma unroll 4
        for (int d = 0; d < 64; d++) {
            float qa[8], kb[4];
            *(float4*)&qa[0] = *(const float4*)&Qt[d * QT_STRIDE + ty * 8];
            *(float4*)&qa[4] = *(const float4*)&Qt[d * QT_STRIDE + ty * 8 + 4];
            *(float4*)&kb[0] = *(const float4*)&Kt[d * KT_STRIDE + tx * 4];
#pragma unroll
            for (int i = 0; i < 8; i++)
#pragma unroll
                for (int j = 0; j < 4; j++)
                    s[i][j] = fmaf(qa[i], kb[j], s[i][j]);
        }

        // scale + mask + online softmax
#pragma unroll
        for (int i = 0; i < 8; i++) {
            const float* mrow = mbase + (size_t)(ty * 8 + i) * TT + k0 + tx * 4;
            float4 mv = *(const float4*)mrow;
            s[i][0] = fmaf(s[i][0], scale, mv.x);
            s[i][1] = fmaf(s[i][1], scale, mv.y);
            s[i][2] = fmaf(s[i][2], scale, mv.z);
            s[i][3] = fmaf(s[i][3], scale, mv.w);

            float mt = fmaxf(fmaxf(s[i][0], s[i][1]), fmaxf(s[i][2], s[i][3]));
#pragma unroll
            for (int off = 8; off; off >>= 1)
                mt = fmaxf(mt, __shfl_xor_sync(0xffffffffu, mt, off, 16));
            float m_new = fmaxf(m_i[i], mt);
            float corr = __expf(m_i[i] - m_new);
            m_i[i] = m_new;

            float rs = 0.0f;
#pragma unroll
            for (int j = 0; j < 4; j++) {
                s[i][j] = __expf(s[i][j] - m_new);
                rs += s[i][j];
            }
#pragma unroll
            for (int off = 8; off; off >>= 1)
                rs += __shfl_xor_sync(0xffffffffu, rs, off, 16);
            l_i[i] = l_i[i] * corr + rs;
#pragma unroll
            for (int j = 0; j < 4; j++) o[i][j] *= corr;
        }

        // Stage P (q-major, float4 stores)
#pragma unroll
        for (int i = 0; i < 8; i++)
            *(float4*)&Ps[(ty * 8 + i) * KT_STRIDE + tx * 4] =
                make_float4(s[i][0], s[i][1], s[i][2], s[i][3]);
        __syncthreads();

        // O += P V
#pragma unroll 2
        for (int kq = 0; kq < 16; kq++) {
            float p[8][4];
#pragma unroll
            for (int i = 0; i < 8; i++)
                *(float4*)&p[i][0] = *(const float4*)&Ps[(ty * 8 + i) * KT_STRIDE + kq * 4];
#pragma unroll
            for (int kk = 0; kk < 4; kk++) {
                float4 vv = *(const float4*)&Vs[(kq * 4 + kk) * KT_STRIDE + tx * 4];
#pragma unroll
                for (int i = 0; i < 8; i++) {
                    o[i][0] = fmaf(p[i][kk], vv.x, o[i][0]);
                    o[i][1] = fmaf(p[i][kk], vv.y, o[i][1]);
                    o[i][2] = fmaf(p[i][kk], vv.z, o[i][2]);
                    o[i][3] = fmaf(p[i][kk], vv.w, o[i][3]);
                }
            }
        }
    }

    // Normalize + write g_att [b*t][D]
#pragma unroll
    for (int i = 0; i < 8; i++) {
        float inv_l = 1.0f / l_i[i];
        size_t row = (size_t)b * TT + (q0 + ty * 8 + i);
        float* arow = g_att + row * DD + h * DHD + tx * 4;
        *(float4*)arow = make_float4(o[i][0] * inv_l, o[i][1] * inv_l,
                                     o[i][2] * inv_l, o[i][3] * inv_l);
    }
}

// ---------------------------------------------------------------------------
// Launch
// ---------------------------------------------------------------------------
extern "C" void kernel_launch(void* const* d_in, const int* in_sizes, int n_in,
                              void* d_out, int out_size)
{
    const float* x      = (const float*)d_in[0];
    const float* mask   = (const float*)d_in[1];
    const float* w_qkv  = (const float*)d_in[2];
    const float* b_qkv  = (const float*)d_in[3];
    const float* w_proj = (const float*)d_in[4];
    const float* b_proj = (const float*)d_in[5];
    float* out = (float*)d_out;

    float* qkv;  cudaGetSymbolAddress((void**)&qkv,  g_qkv);
    float* att;  cudaGetSymbolAddress((void**)&att,  g_att);

    // 1) QKV projection
    {
        dim3 grid(QKVN / GBN, MR / GBM);
        gemm_bias_kernel<<<grid, 256>>>(x, w_qkv, b_qkv, qkv, QKVN, DD);
    }

    // 2) RoPE + scatter
    {
        int total = BB * TT * HH * 32;
        rope_scatter_kernel<<<(total + 255) / 256, 256>>>();
    }

    // 3) Flash attention
    {
        static int smem_set = 0;
        if (!smem_set) {
            cudaFuncSetAttribute(attn_kernel,
                                 cudaFuncAttributeMaxDynamicSharedMemorySize,
                                 ATT_SMEM);
            smem_set = 1;
        }
        dim3 grid(TT / QTILE, BB * HH);
        attn_kernel<<<grid, 256, ATT_SMEM>>>(mask);
    }

    // 4) Output projection
    {
        dim3 grid(DD / GBN, MR / GBM);
        gemm_bias_kernel<<<grid, 256>>>(att, w_proj, b_proj, out, DD, DD);
    }
}

// round 4
// speedup vs baseline: 1.6903x; 1.5592x over previous
#include <cuda_runtime.h>
#include <math.h>

// Problem constants
#define BB   4
#define TT   2048
#define DD   512
#define HH   8
#define DHD  64
#define MR   (BB*TT)       // 8192 rows
#define QKVN (3*DD)        // 1536

// Scratch (device globals -- allocation-free)
__device__ float g_qkv[MR * QKVN];
__device__ float g_q[BB*HH*TT*DHD];       // [b,h,t,d]
__device__ float g_k[BB*HH*TT*DHD];
__device__ float g_v[BB*HH*TT*DHD];
__device__ float g_att[MR * DD];          // [b*t][D]

// ---------------------------------------------------------------------------
// fp32 GEMM: C[M,N] = A[M,K] @ Bw[N,K]^T + bias[N]   (unchanged)
// ---------------------------------------------------------------------------
#define GBM 128
#define GBN 128
#define GBK 16

__global__ __launch_bounds__(256, 2)
void gemm_bias_kernel(const float* __restrict__ A,
                      const float* __restrict__ Bw,
                      const float* __restrict__ bias,
                      float* __restrict__ C,
                      int N, int K)
{
    __shared__ float As[GBK][GBM + 4];
    __shared__ float Bs[GBK][GBN + 4];

    const int tid = threadIdx.x;
    const int tx  = tid & 15;
    const int ty  = tid >> 4;
    const int mBase = blockIdx.y * GBM;
    const int nBase = blockIdx.x * GBN;

    float acc[8][8];
#pragma unroll
    for (int i = 0; i < 8; i++)
#pragma unroll
        for (int j = 0; j < 8; j++) acc[i][j] = 0.0f;

    for (int k0 = 0; k0 < K; k0 += GBK) {
#pragma unroll
        for (int l = 0; l < 2; l++) {
            int f   = tid + l * 256;
            int row = f >> 2;
            int c4  = (f & 3) << 2;
            float4 v = *(const float4*)&A[(size_t)(mBase + row) * K + k0 + c4];
            As[c4 + 0][row] = v.x;
            As[c4 + 1][row] = v.y;
            As[c4 + 2][row] = v.z;
            As[c4 + 3][row] = v.w;
        }
#pragma unroll
        for (int l = 0; l < 2; l++) {
            int f   = tid + l * 256;
            int row = f >> 2;
            int c4  = (f & 3) << 2;
            float4 v = *(const float4*)&Bw[(size_t)(nBase + row) * K + k0 + c4];
            Bs[c4 + 0][row] = v.x;
            Bs[c4 + 1][row] = v.y;
            Bs[c4 + 2][row] = v.z;
            Bs[c4 + 3][row] = v.w;
        }
        __syncthreads();

#pragma unroll
        for (int k = 0; k < GBK; k++) {
            float a[8], bb[8];
            *(float4*)&a[0]  = *(const float4*)&As[k][ty * 8];
            *(float4*)&a[4]  = *(const float4*)&As[k][ty * 8 + 4];
            *(float4*)&bb[0] = *(const float4*)&Bs[k][tx * 8];
            *(float4*)&bb[4] = *(const float4*)&Bs[k][tx * 8 + 4];
#pragma unroll
            for (int i = 0; i < 8; i++)
#pragma unroll
                for (int j = 0; j < 8; j++)
                    acc[i][j] = fmaf(a[i], bb[j], acc[i][j]);
        }
        __syncthreads();
    }

    float bv[8];
#pragma unroll
    for (int j = 0; j < 8; j++) bv[j] = bias[nBase + tx * 8 + j];
#pragma unroll
    for (int i = 0; i < 8; i++) {
        float* crow = &C[(size_t)(mBase + ty * 8 + i) * N + nBase + tx * 8];
        float4 v0 = make_float4(acc[i][0] + bv[0], acc[i][1] + bv[1],
                                acc[i][2] + bv[2], acc[i][3] + bv[3]);
        float4 v1 = make_float4(acc[i][4] + bv[4], acc[i][5] + bv[5],
                                acc[i][6] + bv[6], acc[i][7] + bv[7]);
        *(float4*)&crow[0] = v0;
        *(float4*)&crow[4] = v1;
    }
}

// ---------------------------------------------------------------------------
// RoPE + scatter
// ---------------------------------------------------------------------------
__global__ void rope_scatter_kernel()
{
    int idx = blockIdx.x * blockDim.x + threadIdx.x;
    if (idx >= BB * TT * HH * 32) return;
    const int j  = idx & 31;
    const int h  = (idx >> 5) & 7;
    const int bt = idx >> 8;
    const int b  = bt / TT;
    const int t  = bt - b * TT;

    const float* row = g_qkv + (size_t)bt * QKVN;
    const int base = h * DHD;

    float inv = exp2f(-(float)j * 0.41524103736593f);  // log2(10000)/32
    float ang = (float)t * inv;
    float s, c;
    sincosf(ang, &s, &c);

    float q1 = row[base + j],        q2 = row[base + j + 32];
    float k1 = row[DD + base + j],   k2 = row[DD + base + j + 32];
    float v1 = row[2*DD + base + j], v2 = row[2*DD + base + j + 32];

    size_t o = ((size_t)(b * HH + h) * TT + t) * DHD;
    g_q[o + j]      = q1 * c - q2 * s;
    g_q[o + j + 32] = q2 * c + q1 * s;
    g_k[o + j]      = k1 * c - k2 * s;
    g_k[o + j + 32] = k2 * c + k1 * s;
    g_v[o + j]      = v1;
    g_v[o + j + 32] = v2;
}

// ---------------------------------------------------------------------------
// Flash attention v3: tf32 mma.sync (m16n8k8) for QK^T and PV.
// 128q x 64k tile, 8 warps; warp owns 16 q-rows x full 64 k (softmax stays
// in the 4-lane quad). Q/K/V/P staged in smem pre-rounded to tf32; strides
// chosen so every fragment load pattern is bank-conflict-free.
// ---------------------------------------------------------------------------
#define QTILE 128
#define KTILE 64
#define SQ 68    // stride for Qs/Ks/Ps
#define SV 72    // stride for Vs
#define ATT_SMEM ((QTILE*SQ + KTILE*SQ + KTILE*SV + QTILE*SQ) * 4)

__device__ __forceinline__ float tf32r(float x)
{
    unsigned u;
    asm("cvt.rna.tf32.f32 %0, %1;" : "=r"(u) : "f"(x));
    return __uint_as_float(u);
}

__device__ __forceinline__ void mma_tf32(float c[4],
                                         unsigned a0, unsigned a1,
                                         unsigned a2, unsigned a3,
                                         unsigned b0, unsigned b1)
{
    asm volatile(
        "mma.sync.aligned.m16n8k8.row.col.f32.tf32.tf32.f32 "
        "{%0,%1,%2,%3}, {%4,%5,%6,%7}, {%8,%9}, {%0,%1,%2,%3};"
        : "+f"(c[0]), "+f"(c[1]), "+f"(c[2]), "+f"(c[3])
        : "r"(a0), "r"(a1), "r"(a2), "r"(a3), "r"(b0), "r"(b1));
}

__global__ __launch_bounds__(256, 2)
void attn_kernel(const float* __restrict__ mask)
{
    extern __shared__ float smf[];
    float* Qs = smf;                    // [128][SQ]
    float* Ks = Qs + QTILE * SQ;        // [64][SQ]
    float* Vs = Ks + KTILE * SQ;        // [64][SV]
    float* Ps = Vs + KTILE * SV;        // [128][SQ]

    const int bh   = blockIdx.y;        // 0..31
    const int b    = bh >> 3;
    const int h    = bh & 7;
    const int q0   = blockIdx.x * QTILE;
    const int tid  = threadIdx.x;
    const int warp = tid >> 5;
    const int lane = tid & 31;
    const int gid  = lane >> 2;         // 0..7 (row in frag)
    const int tig  = lane & 3;          // 0..3 (col in frag)
    const int qrow = warp * 16;         // warp's q-row base in tile

    const float scale = 0.125f;

    // Stage Q tile (tf32-rounded), natural [q][d]
    const float* qptr = g_q + ((size_t)bh * TT + q0) * DHD;
    for (int l = tid; l < QTILE * 16; l += 256) {
        int r  = l >> 4;
        int c4 = (l & 15) << 2;
        float4 v = *(const float4*)&qptr[r * DHD + c4];
        v.x = tf32r(v.x); v.y = tf32r(v.y);
        v.z = tf32r(v.z); v.w = tf32r(v.w);
        *(float4*)&Qs[r * SQ + c4] = v;
    }

    float o[8][4];
#pragma unroll
    for (int j = 0; j < 8; j++)
#pragma unroll
        for (int i = 0; i < 4; i++) o[j][i] = 0.0f;
    float m0 = -1e30f, m1 = -1e30f, l0 = 0.0f, l1 = 0.0f;

    const float* kbase = g_k + (size_t)bh * TT * DHD;
    const float* vbase = g_v + (size_t)bh * TT * DHD;
    const float* mrow0base = mask + ((size_t)b * TT + q0 + qrow + gid) * TT;

    for (int kt = 0; kt < TT / KTILE; kt++) {
        const int k0 = kt * KTILE;
        __syncthreads();   // protect Ks/Vs/Ps from previous iteration readers

        // Stage K/V tiles (tf32-rounded)
        const float* kptr = kbase + (size_t)k0 * DHD;
        const float* vptr = vbase + (size_t)k0 * DHD;
        for (int l = tid; l < KTILE * 16; l += 256) {
            int r  = l >> 4;
            int c4 = (l & 15) << 2;
            float4 kv = *(const float4*)&kptr[r * DHD + c4];
            kv.x = tf32r(kv.x); kv.y = tf32r(kv.y);
            kv.z = tf32r(kv.z); kv.w = tf32r(kv.w);
            *(float4*)&Ks[r * SQ + c4] = kv;
            float4 vv = *(const float4*)&vptr[r * DHD + c4];
            vv.x = tf32r(vv.x); vv.y = tf32r(vv.y);
            vv.z = tf32r(vv.z); vv.w = tf32r(vv.w);
            *(float4*)&Vs[r * SV + c4] = vv;
        }
        __syncthreads();

        // ---- S = Q K^T via tf32 mma ----
        float c[8][4];
#pragma unroll
        for (int j = 0; j < 8; j++)
#pragma unroll
            for (int i = 0; i < 4; i++) c[j][i] = 0.0f;

#pragma unroll
        for (int d0 = 0; d0 < 64; d0 += 8) {
            unsigned a0 = __float_as_uint(Qs[(qrow + gid) * SQ + d0 + tig]);
            unsigned a1 = __float_as_uint(Qs[(qrow + gid + 8) * SQ + d0 + tig]);
            unsigned a2 = __float_as_uint(Qs[(qrow + gid) * SQ + d0 + tig + 4]);
            unsigned a3 = __float_as_uint(Qs[(qrow + gid + 8) * SQ + d0 + tig + 4]);
#pragma unroll
            for (int j = 0; j < 8; j++) {
                unsigned b0 = __float_as_uint(Ks[(j * 8 + gid) * SQ + d0 + tig]);
                unsigned b1 = __float_as_uint(Ks[(j * 8 + gid) * SQ + d0 + tig + 4]);
                mma_tf32(c[j], a0, a1, a2, a3, b0, b1);
            }
        }

        // ---- scale + mask ----
        const float* mr0 = mrow0base + k0;
        const float* mr1 = mr0 + 8 * TT;
#pragma unroll
        for (int j = 0; j < 8; j++) {
            float2 mv0 = *(const float2*)&mr0[j * 8 + 2 * tig];
            float2 mv1 = *(const float2*)&mr1[j * 8 + 2 * tig];
            c[j][0] = fmaf(c[j][0], scale, mv0.x);
            c[j][1] = fmaf(c[j][1], scale, mv0.y);
            c[j][2] = fmaf(c[j][2], scale, mv1.x);
            c[j][3] = fmaf(c[j][3], scale, mv1.y);
        }

        // ---- online softmax (rows gid and gid+8; reduce over 4-lane quad) ----
        float mt0 = -1e30f, mt1 = -1e30f;
#pragma unroll
        for (int j = 0; j < 8; j++) {
            mt0 = fmaxf(mt0, fmaxf(c[j][0], c[j][1]));
            mt1 = fmaxf(mt1, fmaxf(c[j][2], c[j][3]));
        }
        mt0 = fmaxf(mt0, __shfl_xor_sync(0xffffffffu, mt0, 1));
        mt0 = fmaxf(mt0, __shfl_xor_sync(0xffffffffu, mt0, 2));
        mt1 = fmaxf(mt1, __shfl_xor_sync(0xffffffffu, mt1, 1));
        mt1 = fmaxf(mt1, __shfl_xor_sync(0xffffffffu, mt1, 2));

        float mn0 = fmaxf(m0, mt0);
        float mn1 = fmaxf(m1, mt1);
        float cor0 = __expf(m0 - mn0);
        float cor1 = __expf(m1 - mn1);
        m0 = mn0; m1 = mn1;

        float rs0 = 0.0f, rs1 = 0.0f;
#pragma unroll
        for (int j = 0; j < 8; j++) {
            c[j][0] = __expf(c[j][0] - mn0);
            c[j][1] = __expf(c[j][1] - mn0);
            c[j][2] = __expf(c[j][2] - mn1);
            c[j][3] = __expf(c[j][3] - mn1);
            rs0 += c[j][0] + c[j][1];
            rs1 += c[j][2] + c[j][3];
        }
        rs0 += __shfl_xor_sync(0xffffffffu, rs0, 1);
        rs0 += __shfl_xor_sync(0xffffffffu, rs0, 2);
        rs1 += __shfl_xor_sync(0xffffffffu, rs1, 1);
        rs1 += __shfl_xor_sync(0xffffffffu, rs1, 2);
        l0 = l0 * cor0 + rs0;
        l1 = l1 * cor1 + rs1;

#pragma unroll
        for (int j = 0; j < 8; j++) {
            o[j][0] *= cor0; o[j][1] *= cor0;
            o[j][2] *= cor1; o[j][3] *= cor1;
        }

        // ---- stage P (tf32-rounded), C-frag layout -> natural [q][k] ----
#pragma unroll
        for (int j = 0; j < 8; j++) {
            *(float2*)&Ps[(qrow + gid) * SQ + j * 8 + 2 * tig] =
                make_float2(tf32r(c[j][0]), tf32r(c[j][1]));
            *(float2*)&Ps[(qrow + gid + 8) * SQ + j * 8 + 2 * tig] =
                make_float2(tf32r(c[j][2]), tf32r(c[j][3]));
        }
        __syncthreads();

        // ---- O += P V via tf32 mma ----
#pragma unroll
        for (int kk0 = 0; kk0 < 64; kk0 += 8) {
            unsigned a0 = __float_as_uint(Ps[(qrow + gid) * SQ + kk0 + tig]);
            unsigned a1 = __float_as_uint(Ps[(qrow + gid + 8) * SQ + kk0 + tig]);
            unsigned a2 = __float_as_uint(Ps[(qrow + gid) * SQ + kk0 + tig + 4]);
            unsigned a3 = __float_as_uint(Ps[(qrow + gid + 8) * SQ + kk0 + tig + 4]);
#pragma unroll
            for (int j = 0; j < 8; j++) {
                unsigned b0 = __float_as_uint(Vs[(kk0 + tig) * SV + j * 8 + gid]);
                unsigned b1 = __float_as_uint(Vs[(kk0 + tig + 4) * SV + j * 8 + gid]);
                mma_tf32(o[j], a0, a1, a2, a3, b0, b1);
            }
        }
    }

    // ---- normalize + write to g_att [b*t][D] ----
    float il0 = 1.0f / l0;
    float il1 = 1.0f / l1;
    size_t r0 = (size_t)b * TT + q0 + qrow + gid;
    float* ap0 = g_att + r0 * DD + h * DHD;
    float* ap1 = ap0 + (size_t)8 * DD;
#pragma unroll
    for (int j = 0; j < 8; j++) {
        *(float2*)&ap0[j * 8 + 2 * tig] = make_float2(o[j][0] * il0, o[j][1] * il0);
        *(float2*)&ap1[j * 8 + 2 * tig] = make_float2(o[j][2] * il1, o[j][3] * il1);
    }
}

// ---------------------------------------------------------------------------
// Launch
// ---------------------------------------------------------------------------
extern "C" void kernel_launch(void* const* d_in, const int* in_sizes, int n_in,
                              void* d_out, int out_size)
{
    const float* x      = (const float*)d_in[0];
    const float* mask   = (const float*)d_in[1];
    const float* w_qkv  = (const float*)d_in[2];
    const float* b_qkv  = (const float*)d_in[3];
    const float* w_proj = (const float*)d_in[4];
    const float* b_proj = (const float*)d_in[5];
    float* out = (float*)d_out;

    float* qkv;  cudaGetSymbolAddress((void**)&qkv,  g_qkv);
    float* att;  cudaGetSymbolAddress((void**)&att,  g_att);

    // 1) QKV projection
    {
        dim3 grid(QKVN / GBN, MR / GBM);
        gemm_bias_kernel<<<grid, 256>>>(x, w_qkv, b_qkv, qkv, QKVN, DD);
    }

    // 2) RoPE + scatter
    {
        int total = BB * TT * HH * 32;
        rope_scatter_kernel<<<(total + 255) / 256, 256>>>();
    }

    // 3) Flash attention (tf32 mma)
    {
        cudaFuncSetAttribute(attn_kernel,
                             cudaFuncAttributeMaxDynamicSharedMemorySize,
                             ATT_SMEM);
        dim3 grid(TT / QTILE, BB * HH);
        attn_kernel<<<grid, 256, ATT_SMEM>>>(mask);
    }

    // 4) Output projection
    {
        dim3 grid(DD / GBN, MR / GBM);
        gemm_bias_kernel<<<grid, 256>>>(att, w_proj, b_proj, out, DD, DD);
    }
}

// round 5
// speedup vs baseline: 2.4883x; 1.4721x over previous
#include <cuda_runtime.h>
#include <math.h>

// Problem constants
#define BB   4
#define TT   2048
#define DD   512
#define HH   8
#define DHD  64
#define MR   (BB*TT)       // 8192 rows
#define QKVN (3*DD)        // 1536

// Scratch (device globals -- allocation-free)
__device__ float g_qkv[MR * QKVN];
__device__ float g_q[BB*HH*TT*DHD];       // [b,h,t,d]
__device__ float g_k[BB*HH*TT*DHD];
__device__ float g_v[BB*HH*TT*DHD];
__device__ float g_att[MR * DD];          // [b*t][D]

// ---------------------------------------------------------------------------
// mma helpers
// ---------------------------------------------------------------------------
__device__ __forceinline__ float tf32r(float x)
{
    unsigned u;
    asm("cvt.rna.tf32.f32 %0, %1;" : "=r"(u) : "f"(x));
    return __uint_as_float(u);
}

__device__ __forceinline__ void mma_tf32(float c[4],
                                         unsigned a0, unsigned a1,
                                         unsigned a2, unsigned a3,
                                         unsigned b0, unsigned b1)
{
    asm volatile(
        "mma.sync.aligned.m16n8k8.row.col.f32.tf32.tf32.f32 "
        "{%0,%1,%2,%3}, {%4,%5,%6,%7}, {%8,%9}, {%0,%1,%2,%3};"
        : "+f"(c[0]), "+f"(c[1]), "+f"(c[2]), "+f"(c[3])
        : "r"(a0), "r"(a1), "r"(a2), "r"(a3), "r"(b0), "r"(b1));
}

// ---------------------------------------------------------------------------
// tf32 GEMM: C[M,N] = A[M,K] @ Bw[N,K]^T + bias[N]
// 128x128x32 tiles, 256 threads (8 warps), warp = 32m x 64n (2x8 mmas).
// As/Bs staged row-major with stride 36 (== 4 mod 32) -> conflict-free frags.
// ---------------------------------------------------------------------------
#define TBM 128
#define TBN 128
#define TBK 32
#define TS  36   // smem stride

__global__ __launch_bounds__(256, 2)
void gemm_tf32_kernel(const float* __restrict__ A,
                      const float* __restrict__ Bw,
                      const float* __restrict__ bias,
                      float* __restrict__ C,
                      int N, int K)
{
    __shared__ float As[TBM * TS];
    __shared__ float Bs[TBN * TS];

    const int tid  = threadIdx.x;
    const int warp = tid >> 5;
    const int lane = tid & 31;
    const int gid  = lane >> 2;        // 0..7
    const int tig  = lane & 3;         // 0..3
    const int mw   = warp >> 1;        // 0..3  -> m base = mw*32
    const int nw   = warp & 1;         // 0..1  -> n base = nw*64

    const int mBase = blockIdx.y * TBM;
    const int nBase = blockIdx.x * TBN;

    float acc[2][8][4];
#pragma unroll
    for (int mi = 0; mi < 2; mi++)
#pragma unroll
        for (int j = 0; j < 8; j++)
#pragma unroll
            for (int i = 0; i < 4; i++) acc[mi][j][i] = 0.0f;

    for (int k0 = 0; k0 < K; k0 += TBK) {
        // Stage A tile 128x32 (tf32-rounded): 1024 float4, 4 per thread
#pragma unroll
        for (int l = 0; l < 4; l++) {
            int f   = tid + l * 256;
            int row = f >> 3;               // 8 float4 per row
            int c4  = (f & 7) << 2;
            float4 v = *(const float4*)&A[(size_t)(mBase + row) * K + k0 + c4];
            v.x = tf32r(v.x); v.y = tf32r(v.y);
            v.z = tf32r(v.z); v.w = tf32r(v.w);
            *(float4*)&As[row * TS + c4] = v;
        }
        // Stage B tile (w[n][k] natural)
#pragma unroll
        for (int l = 0; l < 4; l++) {
            int f   = tid + l * 256;
            int row = f >> 3;
            int c4  = (f & 7) << 2;
            float4 v = *(const float4*)&Bw[(size_t)(nBase + row) * K + k0 + c4];
            v.x = tf32r(v.x); v.y = tf32r(v.y);
            v.z = tf32r(v.z); v.w = tf32r(v.w);
            *(float4*)&Bs[row * TS + c4] = v;
        }
        __syncthreads();

#pragma unroll
        for (int kk = 0; kk < TBK; kk += 8) {
            unsigned a[2][4];
#pragma unroll
            for (int mi = 0; mi < 2; mi++) {
                int r0 = (mw * 32 + mi * 16 + gid) * TS;
                a[mi][0] = __float_as_uint(As[r0 + kk + tig]);
                a[mi][1] = __float_as_uint(As[r0 + 8 * TS + kk + tig]);
                a[mi][2] = __float_as_uint(As[r0 + kk + tig + 4]);
                a[mi][3] = __float_as_uint(As[r0 + 8 * TS + kk + tig + 4]);
            }
#pragma unroll
            for (int j = 0; j < 8; j++) {
                int rb = (nw * 64 + j * 8 + gid) * TS;
                unsigned b0 = __float_as_uint(Bs[rb + kk + tig]);
                unsigned b1 = __float_as_uint(Bs[rb + kk + tig + 4]);
                mma_tf32(acc[0][j], a[0][0], a[0][1], a[0][2], a[0][3], b0, b1);
                mma_tf32(acc[1][j], a[1][0], a[1][1], a[1][2], a[1][3], b0, b1);
            }
        }
        __syncthreads();
    }

    // Epilogue: bias + store (C-frag layout, float2 writes)
#pragma unroll
    for (int mi = 0; mi < 2; mi++) {
        int m0 = mBase + mw * 32 + mi * 16 + gid;
#pragma unroll
        for (int j = 0; j < 8; j++) {
            int col = nBase + nw * 64 + j * 8 + 2 * tig;
            float2 bv = *(const float2*)&bias[col];
            *(float2*)&C[(size_t)m0 * N + col] =
                make_float2(acc[mi][j][0] + bv.x, acc[mi][j][1] + bv.y);
            *(float2*)&C[(size_t)(m0 + 8) * N + col] =
                make_float2(acc[mi][j][2] + bv.x, acc[mi][j][3] + bv.y);
        }
    }
}

// ---------------------------------------------------------------------------
// RoPE + scatter
// ---------------------------------------------------------------------------
__global__ void rope_scatter_kernel()
{
    int idx = blockIdx.x * blockDim.x + threadIdx.x;
    if (idx >= BB * TT * HH * 32) return;
    const int j  = idx & 31;
    const int h  = (idx >> 5) & 7;
    const int bt = idx >> 8;
    const int b  = bt / TT;
    const int t  = bt - b * TT;

    const float* row = g_qkv + (size_t)bt * QKVN;
    const int base = h * DHD;

    float inv = exp2f(-(float)j * 0.41524103736593f);  // log2(10000)/32
    float ang = (float)t * inv;
    float s, c;
    sincosf(ang, &s, &c);

    float q1 = row[base + j],        q2 = row[base + j + 32];
    float k1 = row[DD + base + j],   k2 = row[DD + base + j + 32];
    float v1 = row[2*DD + base + j], v2 = row[2*DD + base + j + 32];

    size_t o = ((size_t)(b * HH + h) * TT + t) * DHD;
    g_q[o + j]      = q1 * c - q2 * s;
    g_q[o + j + 32] = q2 * c + q1 * s;
    g_k[o + j]      = k1 * c - k2 * s;
    g_k[o + j + 32] = k2 * c + k1 * s;
    g_v[o + j]      = v1;
    g_v[o + j + 32] = v2;
}

// ---------------------------------------------------------------------------
// Flash attention (tf32 mma) -- unchanged from R4
// ---------------------------------------------------------------------------
#define QTILE 128
#define KTILE 64
#define SQ 68
#define SV 72
#define ATT_SMEM ((QTILE*SQ + KTILE*SQ + KTILE*SV + QTILE*SQ) * 4)

__global__ __launch_bounds__(256, 2)
void attn_kernel(const float* __restrict__ mask)
{
    extern __shared__ float smf[];
    float* Qs = smf;                    // [128][SQ]
    float* Ks = Qs + QTILE * SQ;        // [64][SQ]
    float* Vs = Ks + KTILE * SQ;        // [64][SV]
    float* Ps = Vs + KTILE * SV;        // [128][SQ]

    const int bh   = blockIdx.y;
    const int b    = bh >> 3;
    const int h    = bh & 7;
    const int q0   = blockIdx.x * QTILE;
    const int tid  = threadIdx.x;
    const int warp = tid >> 5;
    const int lane = tid & 31;
    const int gid  = lane >> 2;
    const int tig  = lane & 3;
    const int qrow = warp * 16;

    const float scale = 0.125f;

    const float* qptr = g_q + ((size_t)bh * TT + q0) * DHD;
    for (int l = tid; l < QTILE * 16; l += 256) {
        int r  = l >> 4;
        int c4 = (l & 15) << 2;
        float4 v = *(const float4*)&qptr[r * DHD + c4];
        v.x = tf32r(v.x); v.y = tf32r(v.y);
        v.z = tf32r(v.z); v.w = tf32r(v.w);
        *(float4*)&Qs[r * SQ + c4] = v;
    }

    float o[8][4];
#pragma unroll
    for (int j = 0; j < 8; j++)
#pragma unroll
        for (int i = 0; i < 4; i++) o[j][i] = 0.0f;
    float m0 = -1e30f, m1 = -1e30f, l0 = 0.0f, l1 = 0.0f;

    const float* kbase = g_k + (size_t)bh * TT * DHD;
    const float* vbase = g_v + (size_t)bh * TT * DHD;
    const float* mrow0base = mask + ((size_t)b * TT + q0 + qrow + gid) * TT;

    for (int kt = 0; kt < TT / KTILE; kt++) {
        const int k0 = kt * KTILE;
        __syncthreads();

        const float* kptr = kbase + (size_t)k0 * DHD;
        const float* vptr = vbase + (size_t)k0 * DHD;
        for (int l = tid; l < KTILE * 16; l += 256) {
            int r  = l >> 4;
            int c4 = (l & 15) << 2;
            float4 kv = *(const float4*)&kptr[r * DHD + c4];
            kv.x = tf32r(kv.x); kv.y = tf32r(kv.y);
            kv.z = tf32r(kv.z); kv.w = tf32r(kv.w);
            *(float4*)&Ks[r * SQ + c4] = kv;
            float4 vv = *(const float4*)&vptr[r * DHD + c4];
            vv.x = tf32r(vv.x); vv.y = tf32r(vv.y);
            vv.z = tf32r(vv.z); vv.w = tf32r(vv.w);
            *(float4*)&Vs[r * SV + c4] = vv;
        }
        __syncthreads();

        float c[8][4];
#pragma unroll
        for (int j = 0; j < 8; j++)
#pragma unroll
            for (int i = 0; i < 4; i++) c[j][i] = 0.0f;

#pragma unroll
        for (int d0 = 0; d0 < 64; d0 += 8) {
            unsigned a0 = __float_as_uint(Qs[(qrow + gid) * SQ + d0 + tig]);
            unsigned a1 = __float_as_uint(Qs[(qrow + gid + 8) * SQ + d0 + tig]);
            unsigned a2 = __float_as_uint(Qs[(qrow + gid) * SQ + d0 + tig + 4]);
            unsigned a3 = __float_as_uint(Qs[(qrow + gid + 8) * SQ + d0 + tig + 4]);
#pragma unroll
            for (int j = 0; j < 8; j++) {
                unsigned b0 = __float_as_uint(Ks[(j * 8 + gid) * SQ + d0 + tig]);
                unsigned b1 = __float_as_uint(Ks[(j * 8 + gid) * SQ + d0 + tig + 4]);
                mma_tf32(c[j], a0, a1, a2, a3, b0, b1);
            }
        }

        const float* mr0 = mrow0base + k0;
        const float* mr1 = mr0 + 8 * TT;
#pragma unroll
        for (int j = 0; j < 8; j++) {
            float2 mv0 = *(const float2*)&mr0[j * 8 + 2 * tig];
            float2 mv1 = *(const float2*)&mr1[j * 8 + 2 * tig];
            c[j][0] = fmaf(c[j][0], scale, mv0.x);
            c[j][1] = fmaf(c[j][1], scale, mv0.y);
            c[j][2] = fmaf(c[j][2], scale, mv1.x);
            c[j][3] = fmaf(c[j][3], scale, mv1.y);
        }

        float mt0 = -1e30f, mt1 = -1e30f;
#pragma unroll
        for (int j = 0; j < 8; j++) {
            mt0 = fmaxf(mt0, fmaxf(c[j][0], c[j][1]));
            mt1 = fmaxf(mt1, fmaxf(c[j][2], c[j][3]));
        }
        mt0 = fmaxf(mt0, __shfl_xor_sync(0xffffffffu, mt0, 1));
        mt0 = fmaxf(mt0, __shfl_xor_sync(0xffffffffu, mt0, 2));
        mt1 = fmaxf(mt1, __shfl_xor_sync(0xffffffffu, mt1, 1));
        mt1 = fmaxf(mt1, __shfl_xor_sync(0xffffffffu, mt1, 2));

        float mn0 = fmaxf(m0, mt0);
        float mn1 = fmaxf(m1, mt1);
        float cor0 = __expf(m0 - mn0);
        float cor1 = __expf(m1 - mn1);
        m0 = mn0; m1 = mn1;

        float rs0 = 0.0f, rs1 = 0.0f;
#pragma unroll
        for (int j = 0; j < 8; j++) {
            c[j][0] = __expf(c[j][0] - mn0);
            c[j][1] = __expf(c[j][1] - mn0);
            c[j][2] = __expf(c[j][2] - mn1);
            c[j][3] = __expf(c[j][3] - mn1);
            rs0 += c[j][0] + c[j][1];
            rs1 += c[j][2] + c[j][3];
        }
        rs0 += __shfl_xor_sync(0xffffffffu, rs0, 1);
        rs0 += __shfl_xor_sync(0xffffffffu, rs0, 2);
        rs1 += __shfl_xor_sync(0xffffffffu, rs1, 1);
        rs1 += __shfl_xor_sync(0xffffffffu, rs1, 2);
        l0 = l0 * cor0 + rs0;
        l1 = l1 * cor1 + rs1;

#pragma unroll
        for (int j = 0; j < 8; j++) {
            o[j][0] *= cor0; o[j][1] *= cor0;
            o[j][2] *= cor1; o[j][3] *= cor1;
        }

#pragma unroll
        for (int j = 0; j < 8; j++) {
            *(float2*)&Ps[(qrow + gid) * SQ + j * 8 + 2 * tig] =
                make_float2(tf32r(c[j][0]), tf32r(c[j][1]));
            *(float2*)&Ps[(qrow + gid + 8) * SQ + j * 8 + 2 * tig] =
                make_float2(tf32r(c[j][2]), tf32r(c[j][3]));
        }
        __syncthreads();

#pragma unroll
        for (int kk0 = 0; kk0 < 64; kk0 += 8) {
            unsigned a0 = __float_as_uint(Ps[(qrow + gid) * SQ + kk0 + tig]);
            unsigned a1 = __float_as_uint(Ps[(qrow + gid + 8) * SQ + kk0 + tig]);
            unsigned a2 = __float_as_uint(Ps[(qrow + gid) * SQ + kk0 + tig + 4]);
            unsigned a3 = __float_as_uint(Ps[(qrow + gid + 8) * SQ + kk0 + tig + 4]);
#pragma unroll
            for (int j = 0; j < 8; j++) {
                unsigned b0 = __float_as_uint(Vs[(kk0 + tig) * SV + j * 8 + gid]);
                unsigned b1 = __float_as_uint(Vs[(kk0 + tig + 4) * SV + j * 8 + gid]);
                mma_tf32(o[j], a0, a1, a2, a3, b0, b1);
            }
        }
    }

    float il0 = 1.0f / l0;
    float il1 = 1.0f / l1;
    size_t r0 = (size_t)b * TT + q0 + qrow + gid;
    float* ap0 = g_att + r0 * DD + h * DHD;
    float* ap1 = ap0 + (size_t)8 * DD;
#pragma unroll
    for (int j = 0; j < 8; j++) {
        *(float2*)&ap0[j * 8 + 2 * tig] = make_float2(o[j][0] * il0, o[j][1] * il0);
        *(float2*)&ap1[j * 8 + 2 * tig] = make_float2(o[j][2] * il1, o[j][3] * il1);
    }
}

// ---------------------------------------------------------------------------
// Launch
// ---------------------------------------------------------------------------
extern "C" void kernel_launch(void* const* d_in, const int* in_sizes, int n_in,
                              void* d_out, int out_size)
{
    const float* x      = (const float*)d_in[0];
    const float* mask   = (const float*)d_in[1];
    const float* w_qkv  = (const float*)d_in[2];
    const float* b_qkv  = (const float*)d_in[3];
    const float* w_proj = (const float*)d_in[4];
    const float* b_proj = (const float*)d_in[5];
    float* out = (float*)d_out;

    float* qkv;  cudaGetSymbolAddress((void**)&qkv,  g_qkv);
    float* att;  cudaGetSymbolAddress((void**)&att,  g_att);

    // 1) QKV projection (tf32 mma)
    {
        dim3 grid(QKVN / TBN, MR / TBM);
        gemm_tf32_kernel<<<grid, 256>>>(x, w_qkv, b_qkv, qkv, QKVN, DD);
    }

    // 2) RoPE + scatter
    {
        int total = BB * TT * HH * 32;
        rope_scatter_kernel<<<(total + 255) / 256, 256>>>();
    }

    // 3) Flash attention (tf32 mma)
    {
        cudaFuncSetAttribute(attn_kernel,
                             cudaFuncAttributeMaxDynamicSharedMemorySize,
                             ATT_SMEM);
        dim3 grid(TT / QTILE, BB * HH);
        attn_kernel<<<grid, 256, ATT_SMEM>>>(mask);
    }

    // 4) Output projection (tf32 mma)
    {
        dim3 grid(DD / TBN, MR / TBM);
        gemm_tf32_kernel<<<grid, 256>>>(att, w_proj, b_proj, out, DD, DD);
    }
}

// round 6
// speedup vs baseline: 2.6332x; 1.0582x over previous
#include <cuda_runtime.h>
#include <math.h>

// Problem constants
#define BB   4
#define TT   2048
#define DD   512
#define HH   8
#define DHD  64
#define MR   (BB*TT)       // 8192
#define QKVN (3*DD)        // 1536

// Scratch (device globals -- allocation-free)
__device__ float g_qkv[MR * QKVN];
__device__ float g_q[BB*HH*TT*DHD];       // [b,h,t,d] (tf32-rounded)
__device__ float g_k[BB*HH*TT*DHD];
__device__ float g_v[BB*HH*TT*DHD];
__device__ float g_att[MR * DD];          // [b*t][D] (tf32-rounded)
__device__ float g_xr[MR * DD];           // x, tf32-rounded
__device__ float g_wqkvr[QKVN * DD];      // w_qkv, tf32-rounded
__device__ float g_wprojr[DD * DD];       // w_proj, tf32-rounded

// ---------------------------------------------------------------------------
// helpers
// ---------------------------------------------------------------------------
__device__ __forceinline__ float tf32r(float x)
{
    unsigned u;
    asm("cvt.rna.tf32.f32 %0, %1;" : "=r"(u) : "f"(x));
    return __uint_as_float(u);
}

__device__ __forceinline__ void mma_tf32(float c[4],
                                         unsigned a0, unsigned a1,
                                         unsigned a2, unsigned a3,
                                         unsigned b0, unsigned b1)
{
    asm volatile(
        "mma.sync.aligned.m16n8k8.row.col.f32.tf32.tf32.f32 "
        "{%0,%1,%2,%3}, {%4,%5,%6,%7}, {%8,%9}, {%0,%1,%2,%3};"
        : "+f"(c[0]), "+f"(c[1]), "+f"(c[2]), "+f"(c[3])
        : "r"(a0), "r"(a1), "r"(a2), "r"(a3), "r"(b0), "r"(b1));
}

__device__ __forceinline__ void cp_async16(unsigned dst, const void* src)
{
    asm volatile("cp.async.cg.shared.global [%0], [%1], 16;\n"
                 :: "r"(dst), "l"(src));
}
__device__ __forceinline__ void cp_commit()
{
    asm volatile("cp.async.commit_group;\n");
}
template<int N> __device__ __forceinline__ void cp_wait()
{
    asm volatile("cp.async.wait_group %0;\n" :: "n"(N));
}

// ---------------------------------------------------------------------------
// pre-round to tf32 (vectorized)
// ---------------------------------------------------------------------------
__global__ void round_tf32_kernel(const float4* __restrict__ src,
                                  float4* __restrict__ dst, int n4)
{
    int i = blockIdx.x * blockDim.x + threadIdx.x;
    if (i < n4) {
        float4 v = src[i];
        v.x = tf32r(v.x); v.y = tf32r(v.y);
        v.z = tf32r(v.z); v.w = tf32r(v.w);
        dst[i] = v;
    }
}

// ---------------------------------------------------------------------------
// tf32 GEMM, cp.async double-buffered: C = A[M,K] @ Bw[N,K]^T + bias
// Inputs MUST already be tf32-rounded. 128x128x32, 8 warps, warp=32m x 64n.
// ---------------------------------------------------------------------------
#define TBM 128
#define TBN 128
#define TBK 32
#define TS  36
#define GEMM_SMEM (2 * 2 * TBM * TS * 4)   // 2 operands x 2 stages

__global__ __launch_bounds__(256, 2)
void gemm_tf32_db_kernel(const float* __restrict__ A,
                         const float* __restrict__ Bw,
                         const float* __restrict__ bias,
                         float* __restrict__ C,
                         int N, int K)
{
    extern __shared__ float gsm[];
    float* As = gsm;                       // [2][TBM*TS]
    float* Bs = gsm + 2 * TBM * TS;        // [2][TBN*TS]

    const int tid  = threadIdx.x;
    const int warp = tid >> 5;
    const int lane = tid & 31;
    const int gid  = lane >> 2;
    const int tig  = lane & 3;
    const int mw   = warp >> 1;
    const int nw   = warp & 1;

    const int mBase = blockIdx.y * TBM;
    const int nBase = blockIdx.x * TBN;

    const unsigned asb = (unsigned)__cvta_generic_to_shared(As);
    const unsigned bsb = (unsigned)__cvta_generic_to_shared(Bs);

    float acc[2][8][4];
#pragma unroll
    for (int mi = 0; mi < 2; mi++)
#pragma unroll
        for (int j = 0; j < 8; j++)
#pragma unroll
            for (int i = 0; i < 4; i++) acc[mi][j][i] = 0.0f;

    const int niter = K / TBK;

    // per-thread copy coords: 4 float4 per operand per stage
    const int crow = tid >> 3;             // 0..31 (x4 via +32)
    const int cc4  = (tid & 7) << 2;       // 0,4,...,28

    auto issue = [&](int kt, int buf) {
        const int k0 = kt * TBK;
        const unsigned abuf = asb + (unsigned)(buf * TBM * TS) * 4u;
        const unsigned bbuf = bsb + (unsigned)(buf * TBN * TS) * 4u;
#pragma unroll
        for (int l = 0; l < 4; l++) {
            int row = crow + l * 32;
            cp_async16(abuf + (unsigned)(row * TS + cc4) * 4u,
                       &A[(size_t)(mBase + row) * K + k0 + cc4]);
        }
#pragma unroll
        for (int l = 0; l < 4; l++) {
            int row = crow + l * 32;
            cp_async16(bbuf + (unsigned)(row * TS + cc4) * 4u,
                       &Bw[(size_t)(nBase + row) * K + k0 + cc4]);
        }
        cp_commit();
    };

    issue(0, 0);

    for (int i = 0; i < niter; i++) {
        if (i + 1 < niter) { issue(i + 1, (i + 1) & 1); cp_wait<1>(); }
        else               { cp_wait<0>(); }
        __syncthreads();

        const float* Ab = As + (i & 1) * TBM * TS;
        const float* Bb = Bs + (i & 1) * TBN * TS;

#pragma unroll
        for (int kk = 0; kk < TBK; kk += 8) {
            unsigned a[2][4];
#pragma unroll
            for (int mi = 0; mi < 2; mi++) {
                int r0 = (mw * 32 + mi * 16 + gid) * TS;
                a[mi][0] = __float_as_uint(Ab[r0 + kk + tig]);
                a[mi][1] = __float_as_uint(Ab[r0 + 8 * TS + kk + tig]);
                a[mi][2] = __float_as_uint(Ab[r0 + kk + tig + 4]);
                a[mi][3] = __float_as_uint(Ab[r0 + 8 * TS + kk + tig + 4]);
            }
#pragma unroll
            for (int j = 0; j < 8; j++) {
                int rb = (nw * 64 + j * 8 + gid) * TS;
                unsigned b0 = __float_as_uint(Bb[rb + kk + tig]);
                unsigned b1 = __float_as_uint(Bb[rb + kk + tig + 4]);
                mma_tf32(acc[0][j], a[0][0], a[0][1], a[0][2], a[0][3], b0, b1);
                mma_tf32(acc[1][j], a[1][0], a[1][1], a[1][2], a[1][3], b0, b1);
            }
        }
        __syncthreads();
    }

    // Epilogue: bias + store
#pragma unroll
    for (int mi = 0; mi < 2; mi++) {
        int m0 = mBase + mw * 32 + mi * 16 + gid;
#pragma unroll
        for (int j = 0; j < 8; j++) {
            int col = nBase + nw * 64 + j * 8 + 2 * tig;
            float2 bv = *(const float2*)&bias[col];
            *(float2*)&C[(size_t)m0 * N + col] =
                make_float2(acc[mi][j][0] + bv.x, acc[mi][j][1] + bv.y);
            *(float2*)&C[(size_t)(m0 + 8) * N + col] =
                make_float2(acc[mi][j][2] + bv.x, acc[mi][j][3] + bv.y);
        }
    }
}

// ---------------------------------------------------------------------------
// RoPE + scatter; outputs tf32-rounded
// ---------------------------------------------------------------------------
__global__ void rope_scatter_kernel()
{
    int idx = blockIdx.x * blockDim.x + threadIdx.x;
    if (idx >= BB * TT * HH * 32) return;
    const int j  = idx & 31;
    const int h  = (idx >> 5) & 7;
    const int bt = idx >> 8;
    const int b  = bt / TT;
    const int t  = bt - b * TT;

    const float* row = g_qkv + (size_t)bt * QKVN;
    const int base = h * DHD;

    float inv = exp2f(-(float)j * 0.41524103736593f);  // log2(10000)/32
    float ang = (float)t * inv;
    float s, c;
    sincosf(ang, &s, &c);

    float q1 = row[base + j],        q2 = row[base + j + 32];
    float k1 = row[DD + base + j],   k2 = row[DD + base + j + 32];
    float v1 = row[2*DD + base + j], v2 = row[2*DD + base + j + 32];

    size_t o = ((size_t)(b * HH + h) * TT + t) * DHD;
    g_q[o + j]      = tf32r(q1 * c - q2 * s);
    g_q[o + j + 32] = tf32r(q2 * c + q1 * s);
    g_k[o + j]      = tf32r(k1 * c - k2 * s);
    g_k[o + j + 32] = tf32r(k2 * c + k1 * s);
    g_v[o + j]      = tf32r(v1);
    g_v[o + j + 32] = tf32r(v2);
}

// ---------------------------------------------------------------------------
// Flash attention v4: tf32 mma, P kept in registers (quad-shuffle C->A frag),
// no P smem round-trip, 2 syncs/tile. Inputs pre-rounded -> staging = copies.
// ---------------------------------------------------------------------------
#define QTILE 128
#define KTILE 64
#define SQ 68
#define SV 72
#define ATT_SMEM ((QTILE*SQ + KTILE*SQ + KTILE*SV) * 4)

__device__ __forceinline__ float shfl4(float v, int src)
{
    return __shfl_sync(0xffffffffu, v, src, 4);
}

__global__ __launch_bounds__(256, 2)
void attn_kernel(const float* __restrict__ mask)
{
    extern __shared__ float smf[];
    float* Qs = smf;                    // [128][SQ]
    float* Ks = Qs + QTILE * SQ;        // [64][SQ]
    float* Vs = Ks + KTILE * SQ;        // [64][SV]

    const int bh   = blockIdx.y;
    const int b    = bh >> 3;
    const int h    = bh & 7;
    const int q0   = blockIdx.x * QTILE;
    const int tid  = threadIdx.x;
    const int warp = tid >> 5;
    const int lane = tid & 31;
    const int gid  = lane >> 2;
    const int tig  = lane & 3;
    const int qrow = warp * 16;

    const float scale = 0.125f;

    // Stage Q (already tf32-rounded)
    const float* qptr = g_q + ((size_t)bh * TT + q0) * DHD;
    for (int l = tid; l < QTILE * 16; l += 256) {
        int r  = l >> 4;
        int c4 = (l & 15) << 2;
        *(float4*)&Qs[r * SQ + c4] = *(const float4*)&qptr[r * DHD + c4];
    }

    float o[8][4];
#pragma unroll
    for (int j = 0; j < 8; j++)
#pragma unroll
        for (int i = 0; i < 4; i++) o[j][i] = 0.0f;
    float m0 = -1e30f, m1 = -1e30f, l0 = 0.0f, l1 = 0.0f;

    const float* kbase = g_k + (size_t)bh * TT * DHD;
    const float* vbase = g_v + (size_t)bh * TT * DHD;
    const float* mrow0base = mask + ((size_t)b * TT + q0 + qrow + gid) * TT;

    for (int kt = 0; kt < TT / KTILE; kt++) {
        const int k0 = kt * KTILE;
        __syncthreads();   // previous tile's PV reads of Vs done

        const float* kptr = kbase + (size_t)k0 * DHD;
        const float* vptr = vbase + (size_t)k0 * DHD;
        for (int l = tid; l < KTILE * 16; l += 256) {
            int r  = l >> 4;
            int c4 = (l & 15) << 2;
            *(float4*)&Ks[r * SQ + c4] = *(const float4*)&kptr[r * DHD + c4];
            *(float4*)&Vs[r * SV + c4] = *(const float4*)&vptr[r * DHD + c4];
        }
        __syncthreads();

        // ---- S = Q K^T ----
        float c[8][4];
#pragma unroll
        for (int j = 0; j < 8; j++)
#pragma unroll
            for (int i = 0; i < 4; i++) c[j][i] = 0.0f;

#pragma unroll
        for (int d0 = 0; d0 < 64; d0 += 8) {
            unsigned a0 = __float_as_uint(Qs[(qrow + gid) * SQ + d0 + tig]);
            unsigned a1 = __float_as_uint(Qs[(qrow + gid + 8) * SQ + d0 + tig]);
            unsigned a2 = __float_as_uint(Qs[(qrow + gid) * SQ + d0 + tig + 4]);
            unsigned a3 = __float_as_uint(Qs[(qrow + gid + 8) * SQ + d0 + tig + 4]);
#pragma unroll
            for (int j = 0; j < 8; j++) {
                unsigned b0 = __float_as_uint(Ks[(j * 8 + gid) * SQ + d0 + tig]);
                unsigned b1 = __float_as_uint(Ks[(j * 8 + gid) * SQ + d0 + tig + 4]);
                mma_tf32(c[j], a0, a1, a2, a3, b0, b1);
            }
        }

        // ---- scale + mask ----
        const float* mr0 = mrow0base + k0;
        const float* mr1 = mr0 + 8 * TT;
#pragma unroll
        for (int j = 0; j < 8; j++) {
            float2 mv0 = *(const float2*)&mr0[j * 8 + 2 * tig];
            float2 mv1 = *(const float2*)&mr1[j * 8 + 2 * tig];
            c[j][0] = fmaf(c[j][0], scale, mv0.x);
            c[j][1] = fmaf(c[j][1], scale, mv0.y);
            c[j][2] = fmaf(c[j][2], scale, mv1.x);
            c[j][3] = fmaf(c[j][3], scale, mv1.y);
        }

        // ---- online softmax (quad reduction) ----
        float mt0 = -1e30f, mt1 = -1e30f;
#pragma unroll
        for (int j = 0; j < 8; j++) {
            mt0 = fmaxf(mt0, fmaxf(c[j][0], c[j][1]));
            mt1 = fmaxf(mt1, fmaxf(c[j][2], c[j][3]));
        }
        mt0 = fmaxf(mt0, __shfl_xor_sync(0xffffffffu, mt0, 1));
        mt0 = fmaxf(mt0, __shfl_xor_sync(0xffffffffu, mt0, 2));
        mt1 = fmaxf(mt1, __shfl_xor_sync(0xffffffffu, mt1, 1));
        mt1 = fmaxf(mt1, __shfl_xor_sync(0xffffffffu, mt1, 2));

        float mn0 = fmaxf(m0, mt0);
        float mn1 = fmaxf(m1, mt1);
        float cor0 = __expf(m0 - mn0);
        float cor1 = __expf(m1 - mn1);
        m0 = mn0; m1 = mn1;

        float rs0 = 0.0f, rs1 = 0.0f;
#pragma unroll
        for (int j = 0; j < 8; j++) {
            c[j][0] = __expf(c[j][0] - mn0);
            c[j][1] = __expf(c[j][1] - mn0);
            c[j][2] = __expf(c[j][2] - mn1);
            c[j][3] = __expf(c[j][3] - mn1);
            rs0 += c[j][0] + c[j][1];
            rs1 += c[j][2] + c[j][3];
        }
        rs0 += __shfl_xor_sync(0xffffffffu, rs0, 1);
        rs0 += __shfl_xor_sync(0xffffffffu, rs0, 2);
        rs1 += __shfl_xor_sync(0xffffffffu, rs1, 1);
        rs1 += __shfl_xor_sync(0xffffffffu, rs1, 2);
        l0 = l0 * cor0 + rs0;
        l1 = l1 * cor1 + rs1;

#pragma unroll
        for (int j = 0; j < 8; j++) {
            o[j][0] *= cor0; o[j][1] *= cor0;
            o[j][2] *= cor1; o[j][3] *= cor1;
        }

        // ---- round P, then O += P V with C->A frag via quad shuffles ----
#pragma unroll
        for (int j = 0; j < 8; j++) {
            c[j][0] = tf32r(c[j][0]); c[j][1] = tf32r(c[j][1]);
            c[j][2] = tf32r(c[j][2]); c[j][3] = tf32r(c[j][3]);
        }

        const int s0  = tig >> 1;
        const int sel = tig & 1;
#pragma unroll
        for (int mblk = 0; mblk < 8; mblk++) {
            // A-frag cols mblk*8 + {tig, tig+4}; source C-frag cols 2t,2t+1
            float x00 = shfl4(c[mblk][0], s0);
            float x01 = shfl4(c[mblk][1], s0);
            float x20 = shfl4(c[mblk][2], s0);
            float x21 = shfl4(c[mblk][3], s0);
            float y00 = shfl4(c[mblk][0], s0 + 2);
            float y01 = shfl4(c[mblk][1], s0 + 2);
            float y20 = shfl4(c[mblk][2], s0 + 2);
            float y21 = shfl4(c[mblk][3], s0 + 2);
            unsigned a0 = __float_as_uint(sel ? x01 : x00);
            unsigned a1 = __float_as_uint(sel ? x21 : x20);
            unsigned a2 = __float_as_uint(sel ? y01 : y00);
            unsigned a3 = __float_as_uint(sel ? y21 : y20);
#pragma unroll
            for (int j = 0; j < 8; j++) {
                unsigned b0 = __float_as_uint(Vs[(mblk * 8 + tig) * SV + j * 8 + gid]);
                unsigned b1 = __float_as_uint(Vs[(mblk * 8 + tig + 4) * SV + j * 8 + gid]);
                mma_tf32(o[j], a0, a1, a2, a3, b0, b1);
            }
        }
    }

    // ---- normalize + write g_att (tf32-rounded for the proj GEMM) ----
    float il0 = 1.0f / l0;
    float il1 = 1.0f / l1;
    size_t r0 = (size_t)b * TT + q0 + qrow + gid;
    float* ap0 = g_att + r0 * DD + h * DHD;
    float* ap1 = ap0 + (size_t)8 * DD;
#pragma unroll
    for (int j = 0; j < 8; j++) {
        *(float2*)&ap0[j * 8 + 2 * tig] =
            make_float2(tf32r(o[j][0] * il0), tf32r(o[j][1] * il0));
        *(float2*)&ap1[j * 8 + 2 * tig] =
            make_float2(tf32r(o[j][2] * il1), tf32r(o[j][3] * il1));
    }
}

// ---------------------------------------------------------------------------
// Launch
// ---------------------------------------------------------------------------
extern "C" void kernel_launch(void* const* d_in, const int* in_sizes, int n_in,
                              void* d_out, int out_size)
{
    const float* x      = (const float*)d_in[0];
    const float* mask   = (const float*)d_in[1];
    const float* w_qkv  = (const float*)d_in[2];
    const float* b_qkv  = (const float*)d_in[3];
    const float* w_proj = (const float*)d_in[4];
    const float* b_proj = (const float*)d_in[5];
    float* out = (float*)d_out;

    float* qkv;   cudaGetSymbolAddress((void**)&qkv,   g_qkv);
    float* att;   cudaGetSymbolAddress((void**)&att,   g_att);
    float* xr;    cudaGetSymbolAddress((void**)&xr,    g_xr);
    float* wqr;   cudaGetSymbolAddress((void**)&wqr,   g_wqkvr);
    float* wpr;   cudaGetSymbolAddress((void**)&wpr,   g_wprojr);

    cudaFuncSetAttribute(gemm_tf32_db_kernel,
                         cudaFuncAttributeMaxDynamicSharedMemorySize, GEMM_SMEM);
    cudaFuncSetAttribute(attn_kernel,
                         cudaFuncAttributeMaxDynamicSharedMemorySize, ATT_SMEM);

    // 0) pre-round inputs to tf32
    {
        int n4 = MR * DD / 4;
        round_tf32_kernel<<<(n4 + 255) / 256, 256>>>((const float4*)x, (float4*)xr, n4);
        n4 = QKVN * DD / 4;
        round_tf32_kernel<<<(n4 + 255) / 256, 256>>>((const float4*)w_qkv, (float4*)wqr, n4);
        n4 = DD * DD / 4;
        round_tf32_kernel<<<(n4 + 255) / 256, 256>>>((const float4*)w_proj, (float4*)wpr, n4);
    }

    // 1) QKV projection
    {
        dim3 grid(QKVN / TBN, MR / TBM);
        gemm_tf32_db_kernel<<<grid, 256, GEMM_SMEM>>>(xr, wqr, b_qkv, qkv, QKVN, DD);
    }

    // 2) RoPE + scatter (tf32-rounded outputs)
    {
        int total = BB * TT * HH * 32;
        rope_scatter_kernel<<<(total + 255) / 256, 256>>>();
    }

    // 3) Flash attention
    {
        dim3 grid(TT / QTILE, BB * HH);
        attn_kernel<<<grid, 256, ATT_SMEM>>>(mask);
    }

    // 4) Output projection
    {
        dim3 grid(DD / TBN, MR / TBM);
        gemm_tf32_db_kernel<<<grid, 256, GEMM_SMEM>>>(att, wpr, b_proj, out, DD, DD);
    }
}

// round 7
// speedup vs baseline: 2.8181x; 1.0702x over previous
#include <cuda_runtime.h>
#include <math.h>

// Problem constants
#define BB   4
#define TT   2048
#define DD   512
#define HH   8
#define DHD  64
#define MR   (BB*TT)       // 8192
#define QKVN (3*DD)        // 1536

// Scratch (device globals -- allocation-free)
__device__ float g_qkv[MR * QKVN];
__device__ float g_q[BB*HH*TT*DHD];       // [b,h,t,d] (tf32-rounded)
__device__ float g_k[BB*HH*TT*DHD];
__device__ float g_v[BB*HH*TT*DHD];
__device__ float g_att[MR * DD];          // [b*t][D] (tf32-rounded)
__device__ float g_xr[MR * DD];           // x, tf32-rounded
__device__ float g_wqkvr[QKVN * DD];      // w_qkv, tf32-rounded
__device__ float g_wprojr[DD * DD];       // w_proj, tf32-rounded

// ---------------------------------------------------------------------------
// helpers
// ---------------------------------------------------------------------------
__device__ __forceinline__ float tf32r(float x)
{
    unsigned u;
    asm("cvt.rna.tf32.f32 %0, %1;" : "=r"(u) : "f"(x));
    return __uint_as_float(u);
}

__device__ __forceinline__ void mma_tf32(float c[4],
                                         unsigned a0, unsigned a1,
                                         unsigned a2, unsigned a3,
                                         unsigned b0, unsigned b1)
{
    asm volatile(
        "mma.sync.aligned.m16n8k8.row.col.f32.tf32.tf32.f32 "
        "{%0,%1,%2,%3}, {%4,%5,%6,%7}, {%8,%9}, {%0,%1,%2,%3};"
        : "+f"(c[0]), "+f"(c[1]), "+f"(c[2]), "+f"(c[3])
        : "r"(a0), "r"(a1), "r"(a2), "r"(a3), "r"(b0), "r"(b1));
}

__device__ __forceinline__ void cp_async16(unsigned dst, const void* src)
{
    asm volatile("cp.async.cg.shared.global [%0], [%1], 16;\n"
                 :: "r"(dst), "l"(src));
}
__device__ __forceinline__ void cp_commit()
{
    asm volatile("cp.async.commit_group;\n");
}
template<int N> __device__ __forceinline__ void cp_wait()
{
    asm volatile("cp.async.wait_group %0;\n" :: "n"(N));
}

// ---------------------------------------------------------------------------
// pre-round to tf32
// ---------------------------------------------------------------------------
__global__ void round_tf32_kernel(const float4* __restrict__ src,
                                  float4* __restrict__ dst, int n4)
{
    int i = blockIdx.x * blockDim.x + threadIdx.x;
    if (i < n4) {
        float4 v = src[i];
        v.x = tf32r(v.x); v.y = tf32r(v.y);
        v.z = tf32r(v.z); v.w = tf32r(v.w);
        dst[i] = v;
    }
}

// ---------------------------------------------------------------------------
// tf32 GEMM, 3-stage cp.async: C = A[M,K] @ Bw[N,K]^T + bias
// Inputs already tf32-rounded. 128x128x32, 8 warps, warp = 32m x 64n.
// ---------------------------------------------------------------------------
#define TBM 128
#define TBN 128
#define TBK 32
#define TS  36
#define NSTG 3
#define GEMM_SMEM (NSTG * 2 * TBM * TS * 4)

__global__ __launch_bounds__(256, 2)
void gemm_tf32_db_kernel(const float* __restrict__ A,
                         const float* __restrict__ Bw,
                         const float* __restrict__ bias,
                         float* __restrict__ C,
                         int N, int K)
{
    extern __shared__ float gsm[];
    float* As = gsm;                          // [NSTG][TBM*TS]
    float* Bs = gsm + NSTG * TBM * TS;        // [NSTG][TBN*TS]

    const int tid  = threadIdx.x;
    const int warp = tid >> 5;
    const int lane = tid & 31;
    const int gid  = lane >> 2;
    const int tig  = lane & 3;
    const int mw   = warp >> 1;
    const int nw   = warp & 1;

    const int mBase = blockIdx.y * TBM;
    const int nBase = blockIdx.x * TBN;

    const unsigned asb = (unsigned)__cvta_generic_to_shared(As);
    const unsigned bsb = (unsigned)__cvta_generic_to_shared(Bs);

    float acc[2][8][4];
#pragma unroll
    for (int mi = 0; mi < 2; mi++)
#pragma unroll
        for (int j = 0; j < 8; j++)
#pragma unroll
            for (int i = 0; i < 4; i++) acc[mi][j][i] = 0.0f;

    const int niter = K / TBK;

    const int crow = tid >> 3;
    const int cc4  = (tid & 7) << 2;

    auto issue = [&](int kt, int buf) {
        const int k0 = kt * TBK;
        const unsigned abuf = asb + (unsigned)(buf * TBM * TS) * 4u;
        const unsigned bbuf = bsb + (unsigned)(buf * TBN * TS) * 4u;
#pragma unroll
        for (int l = 0; l < 4; l++) {
            int row = crow + l * 32;
            cp_async16(abuf + (unsigned)(row * TS + cc4) * 4u,
                       &A[(size_t)(mBase + row) * K + k0 + cc4]);
        }
#pragma unroll
        for (int l = 0; l < 4; l++) {
            int row = crow + l * 32;
            cp_async16(bbuf + (unsigned)(row * TS + cc4) * 4u,
                       &Bw[(size_t)(nBase + row) * K + k0 + cc4]);
        }
        cp_commit();
    };

    issue(0, 0);
    issue(1, 1);

    for (int i = 0; i < niter; i++) {
        if (i + 1 < niter) cp_wait<1>();
        else               cp_wait<0>();
        __syncthreads();
        if (i + 2 < niter) issue(i + 2, (i + 2) % NSTG);

        const int buf = i % NSTG;
        const float* Ab = As + buf * TBM * TS;
        const float* Bb = Bs + buf * TBN * TS;

#pragma unroll
        for (int kk = 0; kk < TBK; kk += 8) {
            unsigned a[2][4];
#pragma unroll
            for (int mi = 0; mi < 2; mi++) {
                int r0 = (mw * 32 + mi * 16 + gid) * TS;
                a[mi][0] = __float_as_uint(Ab[r0 + kk + tig]);
                a[mi][1] = __float_as_uint(Ab[r0 + 8 * TS + kk + tig]);
                a[mi][2] = __float_as_uint(Ab[r0 + kk + tig + 4]);
                a[mi][3] = __float_as_uint(Ab[r0 + 8 * TS + kk + tig + 4]);
            }
#pragma unroll
            for (int j = 0; j < 8; j++) {
                int rb = (nw * 64 + j * 8 + gid) * TS;
                unsigned b0 = __float_as_uint(Bb[rb + kk + tig]);
                unsigned b1 = __float_as_uint(Bb[rb + kk + tig + 4]);
                mma_tf32(acc[0][j], a[0][0], a[0][1], a[0][2], a[0][3], b0, b1);
                mma_tf32(acc[1][j], a[1][0], a[1][1], a[1][2], a[1][3], b0, b1);
            }
        }
        __syncthreads();
    }

    // Epilogue: bias + store
#pragma unroll
    for (int mi = 0; mi < 2; mi++) {
        int m0 = mBase + mw * 32 + mi * 16 + gid;
#pragma unroll
        for (int j = 0; j < 8; j++) {
            int col = nBase + nw * 64 + j * 8 + 2 * tig;
            float2 bv = *(const float2*)&bias[col];
            *(float2*)&C[(size_t)m0 * N + col] =
                make_float2(acc[mi][j][0] + bv.x, acc[mi][j][1] + bv.y);
            *(float2*)&C[(size_t)(m0 + 8) * N + col] =
                make_float2(acc[mi][j][2] + bv.x, acc[mi][j][3] + bv.y);
        }
    }
}

// ---------------------------------------------------------------------------
// RoPE + scatter; outputs tf32-rounded
// ---------------------------------------------------------------------------
__global__ void rope_scatter_kernel()
{
    int idx = blockIdx.x * blockDim.x + threadIdx.x;
    if (idx >= BB * TT * HH * 32) return;
    const int j  = idx & 31;
    const int h  = (idx >> 5) & 7;
    const int bt = idx >> 8;
    const int b  = bt / TT;
    const int t  = bt - b * TT;

    const float* row = g_qkv + (size_t)bt * QKVN;
    const int base = h * DHD;

    float inv = exp2f(-(float)j * 0.41524103736593f);  // log2(10000)/32
    float ang = (float)t * inv;
    float s, c;
    sincosf(ang, &s, &c);

    float q1 = row[base + j],        q2 = row[base + j + 32];
    float k1 = row[DD + base + j],   k2 = row[DD + base + j + 32];
    float v1 = row[2*DD + base + j], v2 = row[2*DD + base + j + 32];

    size_t o = ((size_t)(b * HH + h) * TT + t) * DHD;
    g_q[o + j]      = tf32r(q1 * c - q2 * s);
    g_q[o + j + 32] = tf32r(q2 * c + q1 * s);
    g_k[o + j]      = tf32r(k1 * c - k2 * s);
    g_k[o + j + 32] = tf32r(k2 * c + k1 * s);
    g_v[o + j]      = tf32r(v1);
    g_v[o + j + 32] = tf32r(v2);
}

// ---------------------------------------------------------------------------
// Flash attention v5: tf32 mma, cp.async double-buffered K/V, mask prefetch.
// ---------------------------------------------------------------------------
#define QTILE 128
#define KTILE 64
#define SQ 68
#define SV 72
#define KBUF (KTILE * SQ)       // 4352 floats
#define VBUF (KTILE * SV)       // 4608 floats
#define ATT_SMEM ((QTILE*SQ + 2*KBUF + 2*VBUF) * 4)   // 106496 B

__device__ __forceinline__ float shfl4(float v, int src)
{
    return __shfl_sync(0xffffffffu, v, src, 4);
}

__global__ __launch_bounds__(256, 2)
void attn_kernel(const float* __restrict__ mask)
{
    extern __shared__ float smf[];
    float* Qs = smf;                       // [128][SQ]
    float* Ks = Qs + QTILE * SQ;           // [2][64][SQ]
    float* Vs = Ks + 2 * KBUF;             // [2][64][SV]

    const int bh   = blockIdx.y;
    const int b    = bh >> 3;
    const int h    = bh & 7;
    const int q0   = blockIdx.x * QTILE;
    const int tid  = threadIdx.x;
    const int warp = tid >> 5;
    const int lane = tid & 31;
    const int gid  = lane >> 2;
    const int tig  = lane & 3;
    const int qrow = warp * 16;

    const float scale = 0.125f;

    const unsigned ks_u = (unsigned)__cvta_generic_to_shared(Ks);
    const unsigned vs_u = (unsigned)__cvta_generic_to_shared(Vs);

    const float* kbase = g_k + (size_t)bh * TT * DHD;
    const float* vbase = g_v + (size_t)bh * TT * DHD;

    // per-thread staging coords (4 float4 each for K and V)
    const int srow = tid >> 2;             // 0..63
    const int sc4  = (tid & 3) << 2;       // 0,4,8,12 (of 16 per row -> x4)

    auto issue = [&](int kt, int buf) {
        const int k0 = kt * KTILE;
        const unsigned kb = ks_u + (unsigned)(buf * KBUF) * 4u;
        const unsigned vb = vs_u + (unsigned)(buf * VBUF) * 4u;
        const float* kptr = kbase + (size_t)k0 * DHD;
        const float* vptr = vbase + (size_t)k0 * DHD;
#pragma unroll
        for (int l = 0; l < 4; l++) {
            int c4 = sc4 + l * 16;
            cp_async16(kb + (unsigned)(srow * SQ + c4) * 4u,
                       &kptr[srow * DHD + c4]);
            cp_async16(vb + (unsigned)(srow * SV + c4) * 4u,
                       &vptr[srow * DHD + c4]);
        }
        cp_commit();
    };

    // Stage Q (plain; once)
    const float* qptr = g_q + ((size_t)bh * TT + q0) * DHD;
    for (int l = tid; l < QTILE * 16; l += 256) {
        int r  = l >> 4;
        int c4 = (l & 15) << 2;
        *(float4*)&Qs[r * SQ + c4] = *(const float4*)&qptr[r * DHD + c4];
    }

    issue(0, 0);

    float o[8][4];
#pragma unroll
    for (int j = 0; j < 8; j++)
#pragma unroll
        for (int i = 0; i < 4; i++) o[j][i] = 0.0f;
    float m0 = -1e30f, m1 = -1e30f, l0 = 0.0f, l1 = 0.0f;

    const float* mrow0base = mask + ((size_t)b * TT + q0 + qrow + gid) * TT;

    const int ntiles = TT / KTILE;
    for (int kt = 0; kt < ntiles; kt++) {
        const int k0 = kt * KTILE;

        __syncthreads();   // all warps done with buffer (kt+1)&1 from tile kt-1
        if (kt + 1 < ntiles) { issue(kt + 1, (kt + 1) & 1); cp_wait<1>(); }
        else                 { cp_wait<0>(); }
        __syncthreads();   // tile kt staged & visible

        const float* Kb = Ks + (kt & 1) * KBUF;
        const float* Vb = Vs + (kt & 1) * VBUF;

        // ---- prefetch mask tile into registers (hidden behind QK mmas) ----
        float2 pm0[8], pm1[8];
        {
            const float* mr0 = mrow0base + k0;
            const float* mr1 = mr0 + 8 * TT;
#pragma unroll
            for (int j = 0; j < 8; j++) {
                pm0[j] = *(const float2*)&mr0[j * 8 + 2 * tig];
                pm1[j] = *(const float2*)&mr1[j * 8 + 2 * tig];
            }
        }

        // ---- S = Q K^T ----
        float c[8][4];
#pragma unroll
        for (int j = 0; j < 8; j++)
#pragma unroll
            for (int i = 0; i < 4; i++) c[j][i] = 0.0f;

#pragma unroll
        for (int d0 = 0; d0 < 64; d0 += 8) {
            unsigned a0 = __float_as_uint(Qs[(qrow + gid) * SQ + d0 + tig]);
            unsigned a1 = __float_as_uint(Qs[(qrow + gid + 8) * SQ + d0 + tig]);
            unsigned a2 = __float_as_uint(Qs[(qrow + gid) * SQ + d0 + tig + 4]);
            unsigned a3 = __float_as_uint(Qs[(qrow + gid + 8) * SQ + d0 + tig + 4]);
#pragma unroll
            for (int j = 0; j < 8; j++) {
                unsigned b0 = __float_as_uint(Kb[(j * 8 + gid) * SQ + d0 + tig]);
                unsigned b1 = __float_as_uint(Kb[(j * 8 + gid) * SQ + d0 + tig + 4]);
                mma_tf32(c[j], a0, a1, a2, a3, b0, b1);
            }
        }

        // ---- scale + mask (prefetched) ----
#pragma unroll
        for (int j = 0; j < 8; j++) {
            c[j][0] = fmaf(c[j][0], scale, pm0[j].x);
            c[j][1] = fmaf(c[j][1], scale, pm0[j].y);
            c[j][2] = fmaf(c[j][2], scale, pm1[j].x);
            c[j][3] = fmaf(c[j][3], scale, pm1[j].y);
        }

        // ---- online softmax (quad reduction) ----
        float mt0 = -1e30f, mt1 = -1e30f;
#pragma unroll
        for (int j = 0; j < 8; j++) {
            mt0 = fmaxf(mt0, fmaxf(c[j][0], c[j][1]));
            mt1 = fmaxf(mt1, fmaxf(c[j][2], c[j][3]));
        }
        mt0 = fmaxf(mt0, __shfl_xor_sync(0xffffffffu, mt0, 1));
        mt0 = fmaxf(mt0, __shfl_xor_sync(0xffffffffu, mt0, 2));
        mt1 = fmaxf(mt1, __shfl_xor_sync(0xffffffffu, mt1, 1));
        mt1 = fmaxf(mt1, __shfl_xor_sync(0xffffffffu, mt1, 2));

        float mn0 = fmaxf(m0, mt0);
        float mn1 = fmaxf(m1, mt1);
        float cor0 = __expf(m0 - mn0);
        float cor1 = __expf(m1 - mn1);
        m0 = mn0; m1 = mn1;

        float rs0 = 0.0f, rs1 = 0.0f;
#pragma unroll
        for (int j = 0; j < 8; j++) {
            c[j][0] = __expf(c[j][0] - mn0);
            c[j][1] = __expf(c[j][1] - mn0);
            c[j][2] = __expf(c[j][2] - mn1);
            c[j][3] = __expf(c[j][3] - mn1);
            rs0 += c[j][0] + c[j][1];
            rs1 += c[j][2] + c[j][3];
        }
        rs0 += __shfl_xor_sync(0xffffffffu, rs0, 1);
        rs0 += __shfl_xor_sync(0xffffffffu, rs0, 2);
        rs1 += __shfl_xor_sync(0xffffffffu, rs1, 1);
        rs1 += __shfl_xor_sync(0xffffffffu, rs1, 2);
        l0 = l0 * cor0 + rs0;
        l1 = l1 * cor1 + rs1;

#pragma unroll
        for (int j = 0; j < 8; j++) {
            o[j][0] *= cor0; o[j][1] *= cor0;
            o[j][2] *= cor1; o[j][3] *= cor1;
        }

        // ---- round P; O += P V with C->A frag via quad shuffles ----
#pragma unroll
        for (int j = 0; j < 8; j++) {
            c[j][0] = tf32r(c[j][0]); c[j][1] = tf32r(c[j][1]);
            c[j][2] = tf32r(c[j][2]); c[j][3] = tf32r(c[j][3]);
        }

        const int s0  = tig >> 1;
        const int sel = tig & 1;
#pragma unroll
        for (int mblk = 0; mblk < 8; mblk++) {
            float x00 = shfl4(c[mblk][0], s0);
            float x01 = shfl4(c[mblk][1], s0);
            float x20 = shfl4(c[mblk][2], s0);
            float x21 = shfl4(c[mblk][3], s0);
            float y00 = shfl4(c[mblk][0], s0 + 2);
            float y01 = shfl4(c[mblk][1], s0 + 2);
            float y20 = shfl4(c[mblk][2], s0 + 2);
            float y21 = shfl4(c[mblk][3], s0 + 2);
            unsigned a0 = __float_as_uint(sel ? x01 : x00);
            unsigned a1 = __float_as_uint(sel ? x21 : x20);
            unsigned a2 = __float_as_uint(sel ? y01 : y00);
            unsigned a3 = __float_as_uint(sel ? y21 : y20);
#pragma unroll
            for (int j = 0; j < 8; j++) {
                unsigned b0 = __float_as_uint(Vb[(mblk * 8 + tig) * SV + j * 8 + gid]);
                unsigned b1 = __float_as_uint(Vb[(mblk * 8 + tig + 4) * SV + j * 8 + gid]);
                mma_tf32(o[j], a0, a1, a2, a3, b0, b1);
            }
        }
    }

    // ---- normalize + write g_att (tf32-rounded for proj GEMM) ----
    float il0 = 1.0f / l0;
    float il1 = 1.0f / l1;
    size_t r0 = (size_t)b * TT + q0 + qrow + gid;
    float* ap0 = g_att + r0 * DD + h * DHD;
    float* ap1 = ap0 + (size_t)8 * DD;
#pragma unroll
    for (int j = 0; j < 8; j++) {
        *(float2*)&ap0[j * 8 + 2 * tig] =
            make_float2(tf32r(o[j][0] * il0), tf32r(o[j][1] * il0));
        *(float2*)&ap1[j * 8 + 2 * tig] =
            make_float2(tf32r(o[j][2] * il1), tf32r(o[j][3] * il1));
    }
}

// ---------------------------------------------------------------------------
// Launch
// ---------------------------------------------------------------------------
extern "C" void kernel_launch(void* const* d_in, const int* in_sizes, int n_in,
                              void* d_out, int out_size)
{
    const float* x      = (const float*)d_in[0];
    const float* mask   = (const float*)d_in[1];
    const float* w_qkv  = (const float*)d_in[2];
    const float* b_qkv  = (const float*)d_in[3];
    const float* w_proj = (const float*)d_in[4];
    const float* b_proj = (const float*)d_in[5];
    float* out = (float*)d_out;

    float* qkv;   cudaGetSymbolAddress((void**)&qkv,   g_qkv);
    float* att;   cudaGetSymbolAddress((void**)&att,   g_att);
    float* xr;    cudaGetSymbolAddress((void**)&xr,    g_xr);
    float* wqr;   cudaGetSymbolAddress((void**)&wqr,   g_wqkvr);
    float* wpr;   cudaGetSymbolAddress((void**)&wpr,   g_wprojr);

    cudaFuncSetAttribute(gemm_tf32_db_kernel,
                         cudaFuncAttributeMaxDynamicSharedMemorySize, GEMM_SMEM);
    cudaFuncSetAttribute(attn_kernel,
                         cudaFuncAttributeMaxDynamicSharedMemorySize, ATT_SMEM);

    // 0) pre-round inputs to tf32
    {
        int n4 = MR * DD / 4;
        round_tf32_kernel<<<(n4 + 255) / 256, 256>>>((const float4*)x, (float4*)xr, n4);
        n4 = QKVN * DD / 4;
        round_tf32_kernel<<<(n4 + 255) / 256, 256>>>((const float4*)w_qkv, (float4*)wqr, n4);
        n4 = DD * DD / 4;
        round_tf32_kernel<<<(n4 + 255) / 256, 256>>>((const float4*)w_proj, (float4*)wpr, n4);
    }

    // 1) QKV projection
    {
        dim3 grid(QKVN / TBN, MR / TBM);
        gemm_tf32_db_kernel<<<grid, 256, GEMM_SMEM>>>(xr, wqr, b_qkv, qkv, QKVN, DD);
    }

    // 2) RoPE + scatter
    {
        int total = BB * TT * HH * 32;
        rope_scatter_kernel<<<(total + 255) / 256, 256>>>();
    }

    // 3) Flash attention
    {
        dim3 grid(TT / QTILE, BB * HH);
        attn_kernel<<<grid, 256, ATT_SMEM>>>(mask);
    }

    // 4) Output projection
    {
        dim3 grid(DD / TBN, MR / TBM);
        gemm_tf32_db_kernel<<<grid, 256, GEMM_SMEM>>>(att, wpr, b_proj, out, DD, DD);
    }
}